// round 1
// baseline (speedup 1.0000x reference)
#include <cuda_runtime.h>
#include <math.h>

// Problem constants
#define NN 10000      // nodes
#define EE 100000     // raw edges
#define ET 110000     // edges + self loops
#define CC 200        // channels per head

// ---------------- device scratch (static: no allocation allowed) ----------------
__device__ float g_x[NN * 800];      // layer input features
__device__ float g_h[NN * 800];      // h = x @ W
__device__ float g_asrc[NN * 4];
__device__ float g_adst[NN * 4];
__device__ int   g_deg[NN];
__device__ int   g_rowptr[NN + 1];
__device__ int   g_cursor[NN];
__device__ int   g_srcs[ET];         // CSR-by-dst: source node per slot
__device__ int   g_eid[ET];          // original edge id per slot

static inline int div_up(int a, int b) { return (a + b - 1) / b; }

// ---------------- CSR build ----------------
__global__ void zero_deg_kernel() {
    int i = blockIdx.x * blockDim.x + threadIdx.x;
    if (i < NN) g_deg[i] = 0;
}

__global__ void hist_kernel(const int* __restrict__ ei) {
    int e = blockIdx.x * blockDim.x + threadIdx.x;
    if (e >= ET) return;
    int d = (e < EE) ? ei[EE + e] : (e - EE);
    atomicAdd(&g_deg[d], 1);
}

__global__ void scan_kernel() {
    __shared__ int sh[1024];
    __shared__ int carry;
    int tid = threadIdx.x;
    if (tid == 0) carry = 0;
    __syncthreads();
    for (int base = 0; base < NN; base += 1024) {
        int i = base + tid;
        int v = (i < NN) ? g_deg[i] : 0;
        int x = v;
        #pragma unroll
        for (int off = 1; off < 1024; off <<= 1) {
            sh[tid] = x;
            __syncthreads();
            if (tid >= off) x += sh[tid - off];
            __syncthreads();
        }
        if (i < NN) g_rowptr[i] = carry + x - v;   // exclusive
        sh[tid] = x;
        __syncthreads();
        int total = sh[1023];
        __syncthreads();
        if (tid == 0) carry += total;
        __syncthreads();
    }
    if (threadIdx.x == 0) g_rowptr[NN] = carry;
}

__global__ void cursor_kernel() {
    int i = blockIdx.x * blockDim.x + threadIdx.x;
    if (i < NN) g_cursor[i] = g_rowptr[i];
}

__global__ void scatter_kernel(const int* __restrict__ ei) {
    int e = blockIdx.x * blockDim.x + threadIdx.x;
    if (e >= ET) return;
    int s, d;
    if (e < EE) { s = ei[e]; d = ei[EE + e]; }
    else        { s = e - EE; d = e - EE; }
    int pos = atomicAdd(&g_cursor[d], 1);
    g_srcs[pos] = s;
    g_eid[pos]  = e;
}

// ---------------- SGEMM: C[M,Ncol] = A[M,K] @ B[K,Ncol], fp32, 128x128x8 tile ----------------
#define BM 128
#define BN 128
#define BK 8

__global__ __launch_bounds__(256) void gemm_kernel(
    const float* __restrict__ A, const float* __restrict__ B,
    float* __restrict__ Cm, int M, int K, int Ncol)
{
    __shared__ float As[BK][BM + 4];   // transposed A tile, padded
    __shared__ float Bs[BK][BN];

    int tid = threadIdx.x;             // 256 threads
    int br = blockIdx.y * BM;
    int bc = blockIdx.x * BN;
    int tr = tid >> 4;                 // 0..15
    int tc = tid & 15;                 // 0..15

    float acc[8][8];
    #pragma unroll
    for (int i = 0; i < 8; i++)
        #pragma unroll
        for (int j = 0; j < 8; j++) acc[i][j] = 0.f;

    // A load mapping: one float4 per thread (128 rows x 8 k)
    int a_row = tid >> 1;              // 0..127
    int a_k4  = (tid & 1) * 4;         // 0 or 4
    // B load mapping: one float4 per thread (8 rows x 128 cols)
    int b_row = tid >> 5;              // 0..7
    int b_c   = (tid & 31) * 4;        // 0..124

    for (int k0 = 0; k0 < K; k0 += BK) {
        float4 av = make_float4(0.f, 0.f, 0.f, 0.f);
        int gr = br + a_row;
        if (gr < M) av = *(const float4*)&A[(size_t)gr * K + k0 + a_k4];
        As[a_k4 + 0][a_row] = av.x;
        As[a_k4 + 1][a_row] = av.y;
        As[a_k4 + 2][a_row] = av.z;
        As[a_k4 + 3][a_row] = av.w;

        float4 bv = make_float4(0.f, 0.f, 0.f, 0.f);
        int gc = bc + b_c;
        if (gc < Ncol) bv = *(const float4*)&B[(size_t)(k0 + b_row) * Ncol + gc];
        *(float4*)&Bs[b_row][b_c] = bv;

        __syncthreads();
        #pragma unroll
        for (int kk = 0; kk < BK; kk++) {
            float a[8], b[8];
            *(float4*)&a[0] = *(const float4*)&As[kk][tr * 8];
            *(float4*)&a[4] = *(const float4*)&As[kk][tr * 8 + 4];
            *(float4*)&b[0] = *(const float4*)&Bs[kk][tc * 8];
            *(float4*)&b[4] = *(const float4*)&Bs[kk][tc * 8 + 4];
            #pragma unroll
            for (int i = 0; i < 8; i++)
                #pragma unroll
                for (int j = 0; j < 8; j++)
                    acc[i][j] += a[i] * b[j];
        }
        __syncthreads();
    }

    int cbase = bc + tc * 8;
    bool colok = (cbase < Ncol);       // Ncol % 8 == 0 for all layers
    #pragma unroll
    for (int i = 0; i < 8; i++) {
        int r = br + tr * 8 + i;
        if (r < M && colok) {
            float* cp = &Cm[(size_t)r * Ncol + cbase];
            *(float4*)cp       = make_float4(acc[i][0], acc[i][1], acc[i][2], acc[i][3]);
            *(float4*)(cp + 4) = make_float4(acc[i][4], acc[i][5], acc[i][6], acc[i][7]);
        }
    }
}

// ---------------- alpha_src / alpha_dst: one warp per (node, head) ----------------
__global__ __launch_bounds__(256) void alpha_kernel(
    const float* __restrict__ hfeat, const float* __restrict__ a_src,
    const float* __restrict__ a_dst, int H)
{
    int wid = (blockIdx.x * blockDim.x + threadIdx.x) >> 5;
    int lane = threadIdx.x & 31;
    if (wid >= NN * H) return;
    int n = wid / H, h = wid % H;
    const float* hp = hfeat + (size_t)n * H * CC + h * CC;
    const float* asp = a_src + h * CC;
    const float* adp = a_dst + h * CC;
    float s1 = 0.f, s2 = 0.f;
    for (int c = lane; c < CC; c += 32) {
        float v = hp[c];
        s1 += v * asp[c];
        s2 += v * adp[c];
    }
    #pragma unroll
    for (int o = 16; o; o >>= 1) {
        s1 += __shfl_xor_sync(0xffffffffu, s1, o);
        s2 += __shfl_xor_sync(0xffffffffu, s2, o);
    }
    if (lane == 0) {
        g_asrc[n * H + h] = s1;
        g_adst[n * H + h] = s2;
    }
}

// ---------------- block reduce helper (256 threads) ----------------
__device__ __forceinline__ float block_reduce(float v, bool is_max, float* s8) {
    #pragma unroll
    for (int o = 16; o; o >>= 1) {
        float t = __shfl_xor_sync(0xffffffffu, v, o);
        v = is_max ? fmaxf(v, t) : (v + t);
    }
    int w = threadIdx.x >> 5, lane = threadIdx.x & 31;
    if (lane == 0) s8[w] = v;
    __syncthreads();
    if (threadIdx.x < 8) {
        v = s8[threadIdx.x];
        #pragma unroll
        for (int o = 4; o; o >>= 1) {
            float t = __shfl_xor_sync(0xffu, v, o);
            v = is_max ? fmaxf(v, t) : (v + t);
        }
        if (threadIdx.x == 0) s8[0] = v;
    }
    __syncthreads();
    float r = s8[0];
    __syncthreads();
    return r;
}

// ---------------- segment softmax + weighted aggregation: one block per dst node ----------------
#define AGG_CH 256

__global__ __launch_bounds__(256) void agg_kernel(
    const float* __restrict__ hfeat, const float* __restrict__ bias,
    float* __restrict__ out, float* __restrict__ attn,
    int H, int HC)
{
    int n = blockIdx.x;
    int tid = threadIdx.x;
    int start = g_rowptr[n];
    int deg = g_rowptr[n + 1] - start;

    __shared__ float s8[8];
    __shared__ int   s_src[AGG_CH];
    __shared__ float s_w[AGG_CH * 4];

    float adn[4];
    for (int h = 0; h < H; h++) adn[h] = g_adst[n * H + h];

    // pass 1: per-head max of leaky_relu(asrc[src] + adst[n])
    float lm[4] = {-1e30f, -1e30f, -1e30f, -1e30f};
    for (int j = tid; j < deg; j += 256) {
        int s = g_srcs[start + j];
        for (int h = 0; h < H; h++) {
            float e = g_asrc[s * H + h] + adn[h];
            e = (e > 0.f) ? e : 0.2f * e;
            lm[h] = fmaxf(lm[h], e);
        }
    }
    float m[4];
    for (int h = 0; h < H; h++) m[h] = block_reduce(lm[h], true, s8);

    // pass 2: per-head denominator
    float ls[4] = {0.f, 0.f, 0.f, 0.f};
    for (int j = tid; j < deg; j += 256) {
        int s = g_srcs[start + j];
        for (int h = 0; h < H; h++) {
            float e = g_asrc[s * H + h] + adn[h];
            e = (e > 0.f) ? e : 0.2f * e;
            ls[h] += expf(e - m[h]);
        }
    }
    float invden[4];
    for (int h = 0; h < H; h++) invden[h] = 1.f / block_reduce(ls[h], false, s8);

    // pass 3: chunked weighted accumulation over channels
    float acc[4] = {0.f, 0.f, 0.f, 0.f};
    for (int j0 = 0; j0 < deg; j0 += AGG_CH) {
        int cd = min(AGG_CH, deg - j0);
        __syncthreads();
        for (int j = tid; j < cd; j += 256) {
            int s = g_srcs[start + j0 + j];
            s_src[j] = s;
            for (int h = 0; h < H; h++) {
                float e = g_asrc[s * H + h] + adn[h];
                e = (e > 0.f) ? e : 0.2f * e;
                float w = expf(e - m[h]) * invden[h];
                s_w[j * 4 + h] = w;
                if (attn) attn[g_eid[start + j0 + j]] = w;   // H==1 on last layer
            }
        }
        __syncthreads();
        #pragma unroll
        for (int k = 0; k < 4; k++) {
            int c = tid + k * 256;
            if (c < HC) {
                int h = c / CC;
                float a = acc[k];
                for (int j = 0; j < cd; j++)
                    a += s_w[j * 4 + h] * hfeat[(size_t)s_src[j] * HC + c];
                acc[k] = a;
            }
        }
    }

    // epilogue: bias + exact GELU
    #pragma unroll
    for (int k = 0; k < 4; k++) {
        int c = tid + k * 256;
        if (c < HC) {
            float v = acc[k] + bias[c];
            out[(size_t)n * HC + c] = 0.5f * v * (1.f + erff(v * 0.70710678118654752f));
        }
    }
}

// ---------------- host launch ----------------
extern "C" void kernel_launch(void* const* d_in, const int* in_sizes, int n_in,
                              void* d_out, int out_size)
{
    const float* X  = (const float*)d_in[0];
    const int*   ei = (const int*)d_in[1];
    const float *W[5], *AS[5], *AD[5], *Bb[5];
    for (int i = 0; i < 5; i++) {
        W[i]  = (const float*)d_in[2 + 4 * i];
        AS[i] = (const float*)d_in[3 + 4 * i];
        AD[i] = (const float*)d_in[4 + 4 * i];
        Bb[i] = (const float*)d_in[5 + 4 * i];
    }
    float* out_x = (float*)d_out;
    float* out_a = out_x + (size_t)NN * 200;

    float *px, *ph;
    cudaGetSymbolAddress((void**)&px, g_x);
    cudaGetSymbolAddress((void**)&ph, g_h);

    // ---- CSR build (per launch, deterministic work) ----
    zero_deg_kernel<<<div_up(NN, 256), 256>>>();
    hist_kernel<<<div_up(ET, 256), 256>>>(ei);
    scan_kernel<<<1, 1024>>>();
    cursor_kernel<<<div_up(NN, 256), 256>>>();
    scatter_kernel<<<div_up(ET, 256), 256>>>(ei);

    const int   HEADS[5] = {4, 4, 4, 4, 1};
    const int   FIN[5]   = {200, 800, 800, 800, 800};

    for (int L = 0; L < 5; L++) {
        int H  = HEADS[L];
        int HC = H * CC;
        int K  = FIN[L];
        const float* A = (L == 0) ? X : px;
        dim3 ggrid(div_up(HC, BN), div_up(NN, BM));
        gemm_kernel<<<ggrid, 256>>>(A, W[L], ph, NN, K, HC);

        int nwarps = NN * H;
        alpha_kernel<<<div_up(nwarps * 32, 256), 256>>>(ph, AS[L], AD[L], H);

        float* outp  = (L == 4) ? out_x : px;
        float* attnp = (L == 4) ? out_a : nullptr;
        agg_kernel<<<NN, 256>>>(ph, Bb[L], outp, attnp, H, HC);
    }
    (void)in_sizes; (void)n_in; (void)out_size;
}

// round 4
// speedup vs baseline: 1.4062x; 1.4062x over previous
#include <cuda_runtime.h>
#include <cuda_bf16.h>
#include <math.h>
#include <stdint.h>

// Problem constants
#define NN 10000      // nodes
#define NPAD 10048    // padded rows (multiple of 64)
#define EE 100000     // raw edges
#define ET 110000     // edges + self loops
#define CC 200        // channels per head
#define NB 224        // padded N per head

// ---------------- device scratch ----------------
__device__ float g_x[NN * 800];
__device__ float g_h[NN * 800];
__device__ __align__(256) __nv_bfloat16 g_ahi[NPAD * 800];
__device__ __align__(256) __nv_bfloat16 g_alo[NPAD * 800];
__device__ __align__(256) __nv_bfloat16 g_bhi[4 * NB * 800];
__device__ __align__(256) __nv_bfloat16 g_blo[4 * NB * 800];
__device__ float g_asrc[NN * 4];
__device__ float g_adst[NN * 4];
__device__ int   g_deg[NN];
__device__ int   g_rowptr[NN + 1];
__device__ int   g_cursor[NN];
__device__ int   g_srcs[ET];
__device__ int   g_eid[ET];

static inline int div_up(int a, int b) { return (a + b - 1) / b; }

// ================= PTX helpers (base ISA only) =================
__device__ __forceinline__ uint32_t smem_u32(const void* p) {
    uint32_t a;
    asm("{ .reg .u64 t; cvta.to.shared.u64 t, %1; cvt.u32.u64 %0, t; }" : "=r"(a) : "l"(p));
    return a;
}
#define CP_ASYNC16(dst, src) \
    asm volatile("cp.async.cg.shared.global [%0], [%1], 16;" :: "r"(dst), "l"(src))
#define CP_COMMIT asm volatile("cp.async.commit_group;" ::: "memory")
#define CP_WAIT1  asm volatile("cp.async.wait_group 1;" ::: "memory")
#define CP_WAIT0  asm volatile("cp.async.wait_group 0;" ::: "memory")

__device__ __forceinline__ void ldsm_x4(uint32_t* r, uint32_t addr) {
    asm volatile("ldmatrix.sync.aligned.m8n8.x4.shared.b16 {%0,%1,%2,%3}, [%4];"
        : "=r"(r[0]), "=r"(r[1]), "=r"(r[2]), "=r"(r[3]) : "r"(addr));
}
__device__ __forceinline__ void ldsm_x2(uint32_t* r, uint32_t addr) {
    asm volatile("ldmatrix.sync.aligned.m8n8.x2.shared.b16 {%0,%1}, [%2];"
        : "=r"(r[0]), "=r"(r[1]) : "r"(addr));
}
__device__ __forceinline__ void mma_bf16(float* d, const uint32_t* a, const uint32_t* b) {
    asm volatile("mma.sync.aligned.m16n8k16.row.col.f32.bf16.bf16.f32 "
        "{%0,%1,%2,%3}, {%4,%5,%6,%7}, {%8,%9}, {%0,%1,%2,%3};"
        : "+f"(d[0]), "+f"(d[1]), "+f"(d[2]), "+f"(d[3])
        : "r"(a[0]), "r"(a[1]), "r"(a[2]), "r"(a[3]), "r"(b[0]), "r"(b[1]));
}

// ---------------- CSR build ----------------
__global__ void zero_deg_kernel() {
    int i = blockIdx.x * blockDim.x + threadIdx.x;
    if (i < NN) g_deg[i] = 0;
}
__global__ void hist_kernel(const int* __restrict__ ei) {
    int e = blockIdx.x * blockDim.x + threadIdx.x;
    if (e >= ET) return;
    int d = (e < EE) ? ei[EE + e] : (e - EE);
    atomicAdd(&g_deg[d], 1);
}
__global__ void scan_kernel() {
    __shared__ int sh[1024];
    __shared__ int carry;
    int tid = threadIdx.x;
    if (tid == 0) carry = 0;
    __syncthreads();
    for (int base = 0; base < NN; base += 1024) {
        int i = base + tid;
        int v = (i < NN) ? g_deg[i] : 0;
        int x = v;
        #pragma unroll
        for (int off = 1; off < 1024; off <<= 1) {
            sh[tid] = x;
            __syncthreads();
            if (tid >= off) x += sh[tid - off];
            __syncthreads();
        }
        if (i < NN) g_rowptr[i] = carry + x - v;
        sh[tid] = x;
        __syncthreads();
        int total = sh[1023];
        __syncthreads();
        if (tid == 0) carry += total;
        __syncthreads();
    }
    if (threadIdx.x == 0) g_rowptr[NN] = carry;
}
__global__ void cursor_kernel() {
    int i = blockIdx.x * blockDim.x + threadIdx.x;
    if (i < NN) g_cursor[i] = g_rowptr[i];
}
__global__ void scatter_kernel(const int* __restrict__ ei) {
    int e = blockIdx.x * blockDim.x + threadIdx.x;
    if (e >= ET) return;
    int s, d;
    if (e < EE) { s = ei[e]; d = ei[EE + e]; }
    else        { s = e - EE; d = e - EE; }
    int pos = atomicAdd(&g_cursor[d], 1);
    g_srcs[pos] = s;
    g_eid[pos]  = e;
}

// ---------------- bf16 hi/lo prep ----------------
__device__ __forceinline__ void bf16_split(float v, __nv_bfloat16& h, __nv_bfloat16& l) {
    h = __float2bfloat16(v);
    l = __float2bfloat16(v - __bfloat162float(h));
}

__global__ void prep_a_kernel(const float* __restrict__ A, int K, int Kp) {
    int idx = blockIdx.x * blockDim.x + threadIdx.x;
    if (idx >= NPAD * Kp) return;
    int row = idx / Kp;
    int k = idx - row * Kp;
    float v = (row < NN && k < K) ? A[(size_t)row * K + k] : 0.f;
    __nv_bfloat16 h, l;
    bf16_split(v, h, l);
    g_ahi[idx] = h;
    g_alo[idx] = l;
}

// W [K, HC] -> per-head transposed padded Bt [H][NB][Kp]
__global__ void prep_b_kernel(const float* __restrict__ W, int K, int Kp, int H) {
    int idx = blockIdx.x * blockDim.x + threadIdx.x;
    int total = H * NB * Kp;
    if (idx >= total) return;
    int h = idx / (NB * Kp);
    int rem = idx - h * NB * Kp;
    int n = rem / Kp;
    int k = rem - n * Kp;
    int HC = H * CC;
    float v = (n < CC && k < K) ? W[(size_t)k * HC + h * CC + n] : 0.f;
    __nv_bfloat16 hi, lo;
    bf16_split(v, hi, lo);
    g_bhi[idx] = hi;
    g_blo[idx] = lo;
}

// ================= mma.sync bf16-split GEMM =================
// C[64, 200] tile per block; grid (Mtiles, H).
#define SA_LO 4096u
#define SB_HI 8192u
#define SB_LO 22528u
#define STAGE 36864u
#define CSTRIDE 232
#define GEMM_SMEM (2 * 36864)

__device__ __forceinline__ uint32_t swz(int r, int c) {
    return (uint32_t)(r * 64 + ((c ^ ((r >> 1) & 3)) << 4));
}

__device__ __forceinline__ void fill_stage(
    uint32_t su, int buf, int k0,
    const __nv_bfloat16* __restrict__ ahi, const __nv_bfloat16* __restrict__ alo,
    const __nv_bfloat16* __restrict__ bh, const __nv_bfloat16* __restrict__ bl,
    int Kp, int row0, int tid)
{
    uint32_t sb = su + (uint32_t)buf * STAGE;
    // A: 64 rows x 32 k, 4 x 16B chunks per row (exactly 256 cp.asyncs)
    {
        int r = tid >> 2, c = tid & 3;
        uint32_t da = sb + swz(r, c);
        const char* sa = (const char*)(ahi + (size_t)(row0 + r) * Kp + k0) + c * 16;
        CP_ASYNC16(da, sa);
        const char* sl = (const char*)(alo + (size_t)(row0 + r) * Kp + k0) + c * 16;
        CP_ASYNC16(da + SA_LO, sl);
    }
    // B: 224 rows x 32 k = 896 chunks; 896 = 3*256 + 128 -> guard the tail!
    #pragma unroll
    for (int j0 = 0; j0 < 896; j0 += 256) {
        int j = j0 + tid;
        if (j < 896) {
            int r = j >> 2, c = j & 3;
            uint32_t db = sb + SB_HI + swz(r, c);
            const char* sh = (const char*)(bh + (size_t)r * Kp + k0) + c * 16;
            CP_ASYNC16(db, sh);
            const char* sl = (const char*)(bl + (size_t)r * Kp + k0) + c * 16;
            CP_ASYNC16(db + (SB_LO - SB_HI), sl);
        }
    }
}

__global__ __launch_bounds__(256) void gemm_mma_kernel(
    const __nv_bfloat16* __restrict__ Ahi, const __nv_bfloat16* __restrict__ Alo,
    const __nv_bfloat16* __restrict__ Bhi, const __nv_bfloat16* __restrict__ Blo,
    float* __restrict__ C,
    const float* __restrict__ asv_g, const float* __restrict__ adv_g,
    float* __restrict__ asrc_o, float* __restrict__ adst_o,
    int Kp, int Ncol, int H)
{
    extern __shared__ char smem[];
    uint32_t su = smem_u32(smem);
    int tid = threadIdx.x;
    int w = tid >> 5, lane = tid & 31;
    int mw = w >> 2, nw = w & 3;
    int bm = blockIdx.x, bn = blockIdx.y;
    int row0 = bm * 64;

    const __nv_bfloat16* bh = Bhi + (size_t)bn * NB * Kp;
    const __nv_bfloat16* bl = Blo + (size_t)bn * NB * Kp;

    float acc[2][7][4];
    #pragma unroll
    for (int mf = 0; mf < 2; mf++)
        #pragma unroll
        for (int nf = 0; nf < 7; nf++)
            #pragma unroll
            for (int q = 0; q < 4; q++) acc[mf][nf][q] = 0.f;

    int niter = Kp >> 5;
    fill_stage(su, 0, 0, Ahi, Alo, bh, bl, Kp, row0, tid);
    CP_COMMIT;

    for (int i = 0; i < niter; i++) {
        if (i + 1 < niter) {
            fill_stage(su, (i + 1) & 1, (i + 1) * 32, Ahi, Alo, bh, bl, Kp, row0, tid);
            CP_COMMIT;
            CP_WAIT1;
        } else {
            CP_WAIT0;
        }
        __syncthreads();
        uint32_t sb = su + (uint32_t)(i & 1) * STAGE;
        #pragma unroll
        for (int kk = 0; kk < 2; kk++) {
            uint32_t ah[2][4], al[2][4];
            #pragma unroll
            for (int mf = 0; mf < 2; mf++) {
                int r = mw * 32 + mf * 16 + (lane & 7) + ((lane >> 3) & 1) * 8;
                int ch = 2 * kk + (lane >> 4);
                uint32_t addr = sb + swz(r, ch);
                ldsm_x4(ah[mf], addr);
                ldsm_x4(al[mf], addr + SA_LO);
            }
            #pragma unroll
            for (int nf = 0; nf < 7; nf++) {
                int r = nw * 56 + nf * 8 + (lane & 7);
                int ch = 2 * kk + ((lane >> 3) & 1);
                uint32_t addr = sb + SB_HI + swz(r, ch);
                uint32_t bhv[2], blv[2];
                ldsm_x2(bhv, addr);
                ldsm_x2(blv, addr + (SB_LO - SB_HI));
                #pragma unroll
                for (int mf = 0; mf < 2; mf++) {
                    mma_bf16(acc[mf][nf], ah[mf], bhv);
                    mma_bf16(acc[mf][nf], al[mf], bhv);
                    mma_bf16(acc[mf][nf], ah[mf], blv);
                }
            }
        }
        __syncthreads();
    }

    // ---- epilogue: frags -> smem (row stride 232 covers 224 cols) ----
    float* Cs = (float*)smem;
    #pragma unroll
    for (int mf = 0; mf < 2; mf++) {
        #pragma unroll
        for (int nf = 0; nf < 7; nf++) {
            int r0 = mw * 32 + mf * 16 + (lane >> 2);
            int cb = nw * 56 + nf * 8 + 2 * (lane & 3);
            *(float2*)&Cs[r0 * CSTRIDE + cb] = make_float2(acc[mf][nf][0], acc[mf][nf][1]);
            *(float2*)&Cs[(r0 + 8) * CSTRIDE + cb] = make_float2(acc[mf][nf][2], acc[mf][nf][3]);
        }
    }
    __syncthreads();

    // fused alpha dots: warp w handles rows w*8 .. w*8+7
    const float* asv = asv_g + bn * CC;
    const float* adv = adv_g + bn * CC;
    #pragma unroll
    for (int i = 0; i < 8; i++) {
        int r = w * 8 + i;
        int gr = row0 + r;
        float s1 = 0.f, s2 = 0.f;
        for (int c = lane; c < CC; c += 32) {
            float v = Cs[r * CSTRIDE + c];
            s1 += v * __ldg(asv + c);
            s2 += v * __ldg(adv + c);
        }
        #pragma unroll
        for (int o = 16; o; o >>= 1) {
            s1 += __shfl_xor_sync(0xffffffffu, s1, o);
            s2 += __shfl_xor_sync(0xffffffffu, s2, o);
        }
        if (lane == 0 && gr < NN) {
            asrc_o[gr * H + bn] = s1;
            adst_o[gr * H + bn] = s2;
        }
    }

    // coalesced store of the 200 real columns
    for (int idx = tid; idx < 64 * CC; idx += 256) {
        int r = idx / CC;
        int c = idx - r * CC;
        int gr = row0 + r;
        if (gr < NN)
            C[(size_t)gr * Ncol + bn * CC + c] = Cs[r * CSTRIDE + c];
    }
}

// ---------------- block reduce helper ----------------
__device__ __forceinline__ float block_reduce(float v, bool is_max, float* s8) {
    #pragma unroll
    for (int o = 16; o; o >>= 1) {
        float t = __shfl_xor_sync(0xffffffffu, v, o);
        v = is_max ? fmaxf(v, t) : (v + t);
    }
    int w = threadIdx.x >> 5, lane = threadIdx.x & 31;
    if (lane == 0) s8[w] = v;
    __syncthreads();
    if (threadIdx.x < 8) {
        v = s8[threadIdx.x];
        #pragma unroll
        for (int o = 4; o; o >>= 1) {
            float t = __shfl_xor_sync(0xffu, v, o);
            v = is_max ? fmaxf(v, t) : (v + t);
        }
        if (threadIdx.x == 0) s8[0] = v;
    }
    __syncthreads();
    float r = s8[0];
    __syncthreads();
    return r;
}

// ---------------- segment softmax + weighted aggregation ----------------
#define AGG_CH 256

__global__ __launch_bounds__(256) void agg_kernel(
    const float* __restrict__ hfeat, const float* __restrict__ bias,
    float* __restrict__ out, float* __restrict__ attn,
    int H, int HC)
{
    int n = blockIdx.x;
    int tid = threadIdx.x;
    int start = g_rowptr[n];
    int deg = g_rowptr[n + 1] - start;

    __shared__ float s8[8];
    __shared__ int   s_src[AGG_CH];
    __shared__ float s_w[AGG_CH * 4];

    float adn[4];
    for (int h = 0; h < H; h++) adn[h] = g_adst[n * H + h];

    float lm[4] = {-1e30f, -1e30f, -1e30f, -1e30f};
    for (int j = tid; j < deg; j += 256) {
        int s = g_srcs[start + j];
        for (int h = 0; h < H; h++) {
            float e = g_asrc[s * H + h] + adn[h];
            e = (e > 0.f) ? e : 0.2f * e;
            lm[h] = fmaxf(lm[h], e);
        }
    }
    float m[4];
    for (int h = 0; h < H; h++) m[h] = block_reduce(lm[h], true, s8);

    float ls[4] = {0.f, 0.f, 0.f, 0.f};
    for (int j = tid; j < deg; j += 256) {
        int s = g_srcs[start + j];
        for (int h = 0; h < H; h++) {
            float e = g_asrc[s * H + h] + adn[h];
            e = (e > 0.f) ? e : 0.2f * e;
            ls[h] += expf(e - m[h]);
        }
    }
    float invden[4];
    for (int h = 0; h < H; h++) invden[h] = 1.f / block_reduce(ls[h], false, s8);

    float acc[4] = {0.f, 0.f, 0.f, 0.f};
    for (int j0 = 0; j0 < deg; j0 += AGG_CH) {
        int cd = min(AGG_CH, deg - j0);
        __syncthreads();
        for (int j = tid; j < cd; j += 256) {
            int s = g_srcs[start + j0 + j];
            s_src[j] = s;
            for (int h = 0; h < H; h++) {
                float e = g_asrc[s * H + h] + adn[h];
                e = (e > 0.f) ? e : 0.2f * e;
                float w = expf(e - m[h]) * invden[h];
                s_w[j * 4 + h] = w;
                if (attn) attn[g_eid[start + j0 + j]] = w;
            }
        }
        __syncthreads();
        #pragma unroll
        for (int k = 0; k < 4; k++) {
            int c = tid + k * 256;
            if (c < HC) {
                int h = c / CC;
                float a = acc[k];
                #pragma unroll 4
                for (int j = 0; j < cd; j++)
                    a += s_w[j * 4 + h] * hfeat[(size_t)s_src[j] * HC + c];
                acc[k] = a;
            }
        }
    }

    #pragma unroll
    for (int k = 0; k < 4; k++) {
        int c = tid + k * 256;
        if (c < HC) {
            float v = acc[k] + bias[c];
            out[(size_t)n * HC + c] = 0.5f * v * (1.f + erff(v * 0.70710678118654752f));
        }
    }
}

// ---------------- host launch ----------------
extern "C" void kernel_launch(void* const* d_in, const int* in_sizes, int n_in,
                              void* d_out, int out_size)
{
    const float* X  = (const float*)d_in[0];
    const int*   ei = (const int*)d_in[1];
    const float *W[5], *AS[5], *AD[5], *Bb[5];
    for (int i = 0; i < 5; i++) {
        W[i]  = (const float*)d_in[2 + 4 * i];
        AS[i] = (const float*)d_in[3 + 4 * i];
        AD[i] = (const float*)d_in[4 + 4 * i];
        Bb[i] = (const float*)d_in[5 + 4 * i];
    }
    float* out_x = (float*)d_out;
    float* out_a = out_x + (size_t)NN * 200;

    float *px, *ph, *pas, *pad;
    __nv_bfloat16 *pahi, *palo, *pbhi, *pblo;
    cudaGetSymbolAddress((void**)&px,  g_x);
    cudaGetSymbolAddress((void**)&ph,  g_h);
    cudaGetSymbolAddress((void**)&pas, g_asrc);
    cudaGetSymbolAddress((void**)&pad, g_adst);
    cudaGetSymbolAddress((void**)&pahi, g_ahi);
    cudaGetSymbolAddress((void**)&palo, g_alo);
    cudaGetSymbolAddress((void**)&pbhi, g_bhi);
    cudaGetSymbolAddress((void**)&pblo, g_blo);

    cudaFuncSetAttribute(gemm_mma_kernel, cudaFuncAttributeMaxDynamicSharedMemorySize, GEMM_SMEM);

    // ---- CSR build ----
    zero_deg_kernel<<<div_up(NN, 256), 256>>>();
    hist_kernel<<<div_up(ET, 256), 256>>>(ei);
    scan_kernel<<<1, 1024>>>();
    cursor_kernel<<<div_up(NN, 256), 256>>>();
    scatter_kernel<<<div_up(ET, 256), 256>>>(ei);

    const int HEADS[5] = {4, 4, 4, 4, 1};
    const int FIN[5]   = {200, 800, 800, 800, 800};
    const int MT = NPAD / 64;   // 157 m-tiles

    for (int L = 0; L < 5; L++) {
        int H  = HEADS[L];
        int HC = H * CC;
        int K  = FIN[L];
        int Kp = (K + 31) & ~31;
        const float* A = (L == 0) ? X : px;

        prep_a_kernel<<<div_up(NPAD * Kp, 256), 256>>>(A, K, Kp);
        prep_b_kernel<<<div_up(H * NB * Kp, 256), 256>>>(W[L], K, Kp, H);

        dim3 ggrid(MT, H);
        gemm_mma_kernel<<<ggrid, 256, GEMM_SMEM>>>(
            pahi, palo, pbhi, pblo, ph, AS[L], AD[L], pas, pad, Kp, HC, H);

        float* outp  = (L == 4) ? out_x : px;
        float* attnp = (L == 4) ? out_a : nullptr;
        agg_kernel<<<NN, 256>>>(ph, Bb[L], outp, attnp, H, HC);
    }
    (void)in_sizes; (void)n_in; (void)out_size;
}

// round 8
// speedup vs baseline: 1.6725x; 1.1894x over previous
#include <cuda_runtime.h>
#include <cuda_bf16.h>
#include <math.h>
#include <stdint.h>

// Problem constants
#define NN 10000      // nodes
#define NPAD 10048    // padded rows (multiple of 64)
#define EE 100000     // raw edges
#define ET 110000     // edges + self loops
#define CC 200        // channels per head
#define NB 224        // padded N per head

// ---------------- device scratch ----------------
__device__ __align__(16) float g_h[NN * 800];
__device__ __align__(256) __nv_bfloat16 g_ahi[NPAD * 800];
__device__ __align__(256) __nv_bfloat16 g_alo[NPAD * 800];
__device__ __align__(256) __nv_bfloat16 g_bhi[4 * NB * 800];
__device__ __align__(256) __nv_bfloat16 g_blo[4 * NB * 800];
__device__ float g_asrc[NN * 4];
__device__ float g_adst[NN * 4];
__device__ int   g_deg[NN];
__device__ int   g_rowptr[NN + 1];
__device__ int   g_cursor[NN];
__device__ int   g_srcs[ET];
__device__ int   g_eid[ET];

static inline int div_up(int a, int b) { return (a + b - 1) / b; }

// ================= PTX helpers (base ISA only) =================
__device__ __forceinline__ uint32_t smem_u32(const void* p) {
    uint32_t a;
    asm("{ .reg .u64 t; cvta.to.shared.u64 t, %1; cvt.u32.u64 %0, t; }" : "=r"(a) : "l"(p));
    return a;
}
#define CP_ASYNC16(dst, src) \
    asm volatile("cp.async.cg.shared.global [%0], [%1], 16;" :: "r"(dst), "l"(src))
#define CP_COMMIT asm volatile("cp.async.commit_group;" ::: "memory")
#define CP_WAIT1  asm volatile("cp.async.wait_group 1;" ::: "memory")
#define CP_WAIT0  asm volatile("cp.async.wait_group 0;" ::: "memory")

__device__ __forceinline__ void ldsm_x4(uint32_t* r, uint32_t addr) {
    asm volatile("ldmatrix.sync.aligned.m8n8.x4.shared.b16 {%0,%1,%2,%3}, [%4];"
        : "=r"(r[0]), "=r"(r[1]), "=r"(r[2]), "=r"(r[3]) : "r"(addr));
}
__device__ __forceinline__ void ldsm_x2(uint32_t* r, uint32_t addr) {
    asm volatile("ldmatrix.sync.aligned.m8n8.x2.shared.b16 {%0,%1}, [%2];"
        : "=r"(r[0]), "=r"(r[1]) : "r"(addr));
}
__device__ __forceinline__ void mma_bf16(float* d, const uint32_t* a, const uint32_t* b) {
    asm volatile("mma.sync.aligned.m16n8k16.row.col.f32.bf16.bf16.f32 "
        "{%0,%1,%2,%3}, {%4,%5,%6,%7}, {%8,%9}, {%0,%1,%2,%3};"
        : "+f"(d[0]), "+f"(d[1]), "+f"(d[2]), "+f"(d[3])
        : "r"(a[0]), "r"(a[1]), "r"(a[2]), "r"(a[3]), "r"(b[0]), "r"(b[1]));
}

// ---------------- CSR build ----------------
__global__ void zero_deg_kernel() {
    int i = blockIdx.x * blockDim.x + threadIdx.x;
    if (i < NN) g_deg[i] = 0;
}
__global__ void hist_kernel(const int* __restrict__ ei) {
    int e = blockIdx.x * blockDim.x + threadIdx.x;
    if (e >= ET) return;
    int d = (e < EE) ? ei[EE + e] : (e - EE);
    atomicAdd(&g_deg[d], 1);
}
__global__ void scan_kernel() {
    __shared__ int sh[1024];
    __shared__ int carry;
    int tid = threadIdx.x;
    if (tid == 0) carry = 0;
    __syncthreads();
    for (int base = 0; base < NN; base += 1024) {
        int i = base + tid;
        int v = (i < NN) ? g_deg[i] : 0;
        int x = v;
        #pragma unroll
        for (int off = 1; off < 1024; off <<= 1) {
            sh[tid] = x;
            __syncthreads();
            if (tid >= off) x += sh[tid - off];
            __syncthreads();
        }
        if (i < NN) g_rowptr[i] = carry + x - v;
        sh[tid] = x;
        __syncthreads();
        int total = sh[1023];
        __syncthreads();
        if (tid == 0) carry += total;
        __syncthreads();
    }
    if (threadIdx.x == 0) g_rowptr[NN] = carry;
}
__global__ void cursor_kernel() {
    int i = blockIdx.x * blockDim.x + threadIdx.x;
    if (i < NN) g_cursor[i] = g_rowptr[i];
}
__global__ void scatter_kernel(const int* __restrict__ ei) {
    int e = blockIdx.x * blockDim.x + threadIdx.x;
    if (e >= ET) return;
    int s, d;
    if (e < EE) { s = ei[e]; d = ei[EE + e]; }
    else        { s = e - EE; d = e - EE; }
    int pos = atomicAdd(&g_cursor[d], 1);
    g_srcs[pos] = s;
    g_eid[pos]  = e;
}

// ---------------- bf16 hi/lo prep ----------------
__device__ __forceinline__ void bf16_split(float v, __nv_bfloat16& h, __nv_bfloat16& l) {
    h = __float2bfloat16(v);
    l = __float2bfloat16(v - __bfloat162float(h));
}

// X -> g_ahi/g_alo (layer 0 only)
__global__ void prep_a_kernel(const float* __restrict__ A, int K, int Kp) {
    int idx = blockIdx.x * blockDim.x + threadIdx.x;
    if (idx >= NPAD * Kp) return;
    int row = idx / Kp;
    int k = idx - row * Kp;
    float v = (row < NN && k < K) ? A[(size_t)row * K + k] : 0.f;
    __nv_bfloat16 h, l;
    bf16_split(v, h, l);
    g_ahi[idx] = h;
    g_alo[idx] = l;
}

// zero the 48 pad rows at stride 800 (used by layers 1-4)
__global__ void zero_pad_kernel() {
    int idx = blockIdx.x * blockDim.x + threadIdx.x;
    int total = (NPAD - NN) * 800;
    if (idx >= total) return;
    int off = NN * 800 + idx;
    g_ahi[off] = __float2bfloat16(0.f);
    g_alo[off] = __float2bfloat16(0.f);
}

// W [K, HC] -> per-head transposed padded Bt [H][NB][Kp]
__global__ void prep_b_kernel(const float* __restrict__ W, int K, int Kp, int H) {
    int idx = blockIdx.x * blockDim.x + threadIdx.x;
    int total = H * NB * Kp;
    if (idx >= total) return;
    int h = idx / (NB * Kp);
    int rem = idx - h * NB * Kp;
    int n = rem / Kp;
    int k = rem - n * Kp;
    int HC = H * CC;
    float v = (n < CC && k < K) ? W[(size_t)k * HC + h * CC + n] : 0.f;
    __nv_bfloat16 hi, lo;
    bf16_split(v, hi, lo);
    g_bhi[idx] = hi;
    g_blo[idx] = lo;
}

// ================= mma.sync bf16-split GEMM =================
#define SA_LO 4096u
#define SB_HI 8192u
#define SB_LO 22528u
#define STAGE 36864u
#define CSTRIDE 232
#define GEMM_SMEM (2 * 36864)

__device__ __forceinline__ uint32_t swz(int r, int c) {
    return (uint32_t)(r * 64 + ((c ^ ((r >> 1) & 3)) << 4));
}

__device__ __forceinline__ void fill_stage(
    uint32_t su, int buf, int k0,
    const __nv_bfloat16* __restrict__ ahi, const __nv_bfloat16* __restrict__ alo,
    const __nv_bfloat16* __restrict__ bh, const __nv_bfloat16* __restrict__ bl,
    int Kp, int row0, int tid)
{
    uint32_t sb = su + (uint32_t)buf * STAGE;
    {
        int r = tid >> 2, c = tid & 3;
        uint32_t da = sb + swz(r, c);
        const char* sa = (const char*)(ahi + (size_t)(row0 + r) * Kp + k0) + c * 16;
        CP_ASYNC16(da, sa);
        const char* sl = (const char*)(alo + (size_t)(row0 + r) * Kp + k0) + c * 16;
        CP_ASYNC16(da + SA_LO, sl);
    }
    #pragma unroll
    for (int j0 = 0; j0 < 896; j0 += 256) {
        int j = j0 + tid;
        if (j < 896) {
            int r = j >> 2, c = j & 3;
            uint32_t db = sb + SB_HI + swz(r, c);
            const char* sh = (const char*)(bh + (size_t)r * Kp + k0) + c * 16;
            CP_ASYNC16(db, sh);
            const char* sl = (const char*)(bl + (size_t)r * Kp + k0) + c * 16;
            CP_ASYNC16(db + (SB_LO - SB_HI), sl);
        }
    }
}

__global__ __launch_bounds__(256) void gemm_mma_kernel(
    const __nv_bfloat16* __restrict__ Ahi, const __nv_bfloat16* __restrict__ Alo,
    const __nv_bfloat16* __restrict__ Bhi, const __nv_bfloat16* __restrict__ Blo,
    float* __restrict__ C,
    const float* __restrict__ asv_g, const float* __restrict__ adv_g,
    float* __restrict__ asrc_o, float* __restrict__ adst_o,
    int Kp, int Ncol, int H)
{
    extern __shared__ char smem[];
    uint32_t su = smem_u32(smem);
    int tid = threadIdx.x;
    int w = tid >> 5, lane = tid & 31;
    int mw = w >> 2, nw = w & 3;
    int bm = blockIdx.x, bn = blockIdx.y;
    int row0 = bm * 64;

    const __nv_bfloat16* bhp = Bhi + (size_t)bn * NB * Kp;
    const __nv_bfloat16* blp = Blo + (size_t)bn * NB * Kp;

    float acc[2][7][4];
    #pragma unroll
    for (int mf = 0; mf < 2; mf++)
        #pragma unroll
        for (int nf = 0; nf < 7; nf++)
            #pragma unroll
            for (int q = 0; q < 4; q++) acc[mf][nf][q] = 0.f;

    int niter = Kp >> 5;
    fill_stage(su, 0, 0, Ahi, Alo, bhp, blp, Kp, row0, tid);
    CP_COMMIT;

    for (int i = 0; i < niter; i++) {
        if (i + 1 < niter) {
            fill_stage(su, (i + 1) & 1, (i + 1) * 32, Ahi, Alo, bhp, blp, Kp, row0, tid);
            CP_COMMIT;
            CP_WAIT1;
        } else {
            CP_WAIT0;
        }
        __syncthreads();
        uint32_t sb = su + (uint32_t)(i & 1) * STAGE;
        #pragma unroll
        for (int kk = 0; kk < 2; kk++) {
            // ---- load all B frags for this kk (paired x4) ----
            uint32_t bh[7][2], bl[7][2];
            {
                int g = lane >> 3;
                #pragma unroll
                for (int p = 0; p < 3; p++) {
                    int nf = p * 2;
                    int r = nw * 56 + (nf + (g >> 1)) * 8 + (lane & 7);
                    int ch = 2 * kk + (g & 1);
                    uint32_t addr = sb + SB_HI + swz(r, ch);
                    uint32_t t[4];
                    ldsm_x4(t, addr);
                    bh[nf][0] = t[0]; bh[nf][1] = t[1];
                    bh[nf + 1][0] = t[2]; bh[nf + 1][1] = t[3];
                    ldsm_x4(t, addr + (SB_LO - SB_HI));
                    bl[nf][0] = t[0]; bl[nf][1] = t[1];
                    bl[nf + 1][0] = t[2]; bl[nf + 1][1] = t[3];
                }
                int r = nw * 56 + 48 + (lane & 7);
                int ch = 2 * kk + ((lane >> 3) & 1);
                uint32_t addr = sb + SB_HI + swz(r, ch);
                ldsm_x2(bh[6], addr);
                ldsm_x2(bl[6], addr + (SB_LO - SB_HI));
            }
            // ---- load A frags ----
            uint32_t ah[2][4], al[2][4];
            #pragma unroll
            for (int mf = 0; mf < 2; mf++) {
                int r = mw * 32 + mf * 16 + (lane & 7) + ((lane >> 3) & 1) * 8;
                int ch = 2 * kk + (lane >> 4);
                uint32_t addr = sb + swz(r, ch);
                ldsm_x4(ah[mf], addr);
                ldsm_x4(al[mf], addr + SA_LO);
            }
            // ---- three independent sweeps (14 independent MMAs each) ----
            #pragma unroll
            for (int nf = 0; nf < 7; nf++)
                #pragma unroll
                for (int mf = 0; mf < 2; mf++)
                    mma_bf16(acc[mf][nf], ah[mf], bh[nf]);
            #pragma unroll
            for (int nf = 0; nf < 7; nf++)
                #pragma unroll
                for (int mf = 0; mf < 2; mf++)
                    mma_bf16(acc[mf][nf], al[mf], bh[nf]);
            #pragma unroll
            for (int nf = 0; nf < 7; nf++)
                #pragma unroll
                for (int mf = 0; mf < 2; mf++)
                    mma_bf16(acc[mf][nf], ah[mf], bl[nf]);
        }
        __syncthreads();
    }

    // ---- epilogue: frags -> smem ----
    float* Cs = (float*)smem;
    #pragma unroll
    for (int mf = 0; mf < 2; mf++) {
        #pragma unroll
        for (int nf = 0; nf < 7; nf++) {
            int r0 = mw * 32 + mf * 16 + (lane >> 2);
            int cb = nw * 56 + nf * 8 + 2 * (lane & 3);
            *(float2*)&Cs[r0 * CSTRIDE + cb] = make_float2(acc[mf][nf][0], acc[mf][nf][1]);
            *(float2*)&Cs[(r0 + 8) * CSTRIDE + cb] = make_float2(acc[mf][nf][2], acc[mf][nf][3]);
        }
    }
    __syncthreads();

    // fused alpha dots: warp w handles rows w*8 .. w*8+7
    const float* asv = asv_g + bn * CC;
    const float* adv = adv_g + bn * CC;
    #pragma unroll
    for (int i = 0; i < 8; i++) {
        int r = w * 8 + i;
        int gr = row0 + r;
        float s1 = 0.f, s2 = 0.f;
        for (int c = lane; c < CC; c += 32) {
            float v = Cs[r * CSTRIDE + c];
            s1 += v * __ldg(asv + c);
            s2 += v * __ldg(adv + c);
        }
        #pragma unroll
        for (int o = 16; o; o >>= 1) {
            s1 += __shfl_xor_sync(0xffffffffu, s1, o);
            s2 += __shfl_xor_sync(0xffffffffu, s2, o);
        }
        if (lane == 0 && gr < NN) {
            asrc_o[gr * H + bn] = s1;
            adst_o[gr * H + bn] = s2;
        }
    }

    // coalesced store of the 200 real columns
    for (int idx = tid; idx < 64 * CC; idx += 256) {
        int r = idx / CC;
        int c = idx - r * CC;
        int gr = row0 + r;
        if (gr < NN)
            C[(size_t)gr * Ncol + bn * CC + c] = Cs[r * CSTRIDE + c];
    }
}

// ---------------- block reduce helper ----------------
__device__ __forceinline__ float block_reduce(float v, bool is_max, float* s8) {
    #pragma unroll
    for (int o = 16; o; o >>= 1) {
        float t = __shfl_xor_sync(0xffffffffu, v, o);
        v = is_max ? fmaxf(v, t) : (v + t);
    }
    int w = threadIdx.x >> 5, lane = threadIdx.x & 31;
    if (lane == 0) s8[w] = v;
    __syncthreads();
    if (threadIdx.x < 8) {
        v = s8[threadIdx.x];
        #pragma unroll
        for (int o = 4; o; o >>= 1) {
            float t = __shfl_xor_sync(0xffu, v, o);
            v = is_max ? fmaxf(v, t) : (v + t);
        }
        if (threadIdx.x == 0) s8[0] = v;
    }
    __syncthreads();
    float r = s8[0];
    __syncthreads();
    return r;
}

// ---------------- segment softmax + weighted aggregation ----------------
// NOTE: `out` may be nullptr (inner layers) — the float result is consumed
// only via the fused bf16 hi/lo buffers (ahi_o/alo_o). Writing `out` into
// hfeat's buffer would be a cross-block read/write race.
#define AGG_CH 256

__global__ __launch_bounds__(256) void agg_kernel(
    const float* __restrict__ hfeat, const float* __restrict__ bias,
    float* __restrict__ out, float* __restrict__ attn,
    __nv_bfloat16* __restrict__ ahi_o, __nv_bfloat16* __restrict__ alo_o,
    int H, int HC)
{
    int n = blockIdx.x;
    int tid = threadIdx.x;
    int start = g_rowptr[n];
    int deg = g_rowptr[n + 1] - start;

    __shared__ float s8[8];
    __shared__ int   s_src[AGG_CH];
    __shared__ float s_w[AGG_CH * 4];

    float adn[4];
    for (int h = 0; h < H; h++) adn[h] = g_adst[n * H + h];

    float lm[4] = {-1e30f, -1e30f, -1e30f, -1e30f};
    for (int j = tid; j < deg; j += 256) {
        int s = g_srcs[start + j];
        for (int h = 0; h < H; h++) {
            float e = g_asrc[s * H + h] + adn[h];
            e = (e > 0.f) ? e : 0.2f * e;
            lm[h] = fmaxf(lm[h], e);
        }
    }
    float m[4];
    for (int h = 0; h < H; h++) m[h] = block_reduce(lm[h], true, s8);

    float ls[4] = {0.f, 0.f, 0.f, 0.f};
    for (int j = tid; j < deg; j += 256) {
        int s = g_srcs[start + j];
        for (int h = 0; h < H; h++) {
            float e = g_asrc[s * H + h] + adn[h];
            e = (e > 0.f) ? e : 0.2f * e;
            ls[h] += expf(e - m[h]);
        }
    }
    float invden[4];
    for (int h = 0; h < H; h++) invden[h] = 1.f / block_reduce(ls[h], false, s8);

    // pass 3: each thread owns one float4 of channels
    int nch4 = HC >> 2;
    int c4 = tid;
    int h4 = (4 * c4) / CC;
    float4 a4 = make_float4(0.f, 0.f, 0.f, 0.f);

    for (int j0 = 0; j0 < deg; j0 += AGG_CH) {
        int cd = min(AGG_CH, deg - j0);
        __syncthreads();
        for (int j = tid; j < cd; j += 256) {
            int s = g_srcs[start + j0 + j];
            s_src[j] = s;
            for (int h = 0; h < H; h++) {
                float e = g_asrc[s * H + h] + adn[h];
                e = (e > 0.f) ? e : 0.2f * e;
                float wv = expf(e - m[h]) * invden[h];
                s_w[j * 4 + h] = wv;
                if (attn) attn[g_eid[start + j0 + j]] = wv;
            }
        }
        __syncthreads();
        if (c4 < nch4) {
            const float* hp = hfeat + 4 * c4;
            #pragma unroll 2
            for (int j = 0; j < cd; j++) {
                float wv = s_w[j * 4 + h4];
                float4 v = *(const float4*)(hp + (size_t)s_src[j] * HC);
                a4.x += wv * v.x; a4.y += wv * v.y;
                a4.z += wv * v.z; a4.w += wv * v.w;
            }
        }
    }

    if (c4 < nch4) {
        float4 b4 = *(const float4*)&bias[4 * c4];
        float4 o4;
        o4.x = a4.x + b4.x; o4.y = a4.y + b4.y;
        o4.z = a4.z + b4.z; o4.w = a4.w + b4.w;
        const float k = 0.70710678118654752f;
        o4.x = 0.5f * o4.x * (1.f + erff(o4.x * k));
        o4.y = 0.5f * o4.y * (1.f + erff(o4.y * k));
        o4.z = 0.5f * o4.z * (1.f + erff(o4.z * k));
        o4.w = 0.5f * o4.w * (1.f + erff(o4.w * k));
        if (out)
            *(float4*)&out[(size_t)n * HC + 4 * c4] = o4;
        if (ahi_o) {
            size_t base = (size_t)n * 800 + 4 * c4;
            __nv_bfloat16 hx, lx, hy, ly, hz, lz, hw, lw;
            bf16_split(o4.x, hx, lx); bf16_split(o4.y, hy, ly);
            bf16_split(o4.z, hz, lz); bf16_split(o4.w, hw, lw);
            *(__nv_bfloat162*)&ahi_o[base]     = __nv_bfloat162(hx, hy);
            *(__nv_bfloat162*)&ahi_o[base + 2] = __nv_bfloat162(hz, hw);
            *(__nv_bfloat162*)&alo_o[base]     = __nv_bfloat162(lx, ly);
            *(__nv_bfloat162*)&alo_o[base + 2] = __nv_bfloat162(lz, lw);
        }
    }
}

// ---------------- host launch ----------------
extern "C" void kernel_launch(void* const* d_in, const int* in_sizes, int n_in,
                              void* d_out, int out_size)
{
    const float* X  = (const float*)d_in[0];
    const int*   ei = (const int*)d_in[1];
    const float *W[5], *AS[5], *AD[5], *Bb[5];
    for (int i = 0; i < 5; i++) {
        W[i]  = (const float*)d_in[2 + 4 * i];
        AS[i] = (const float*)d_in[3 + 4 * i];
        AD[i] = (const float*)d_in[4 + 4 * i];
        Bb[i] = (const float*)d_in[5 + 4 * i];
    }
    float* out_x = (float*)d_out;
    float* out_a = out_x + (size_t)NN * 200;

    float *ph, *pas, *pad;
    __nv_bfloat16 *pahi, *palo, *pbhi, *pblo;
    cudaGetSymbolAddress((void**)&ph,  g_h);
    cudaGetSymbolAddress((void**)&pas, g_asrc);
    cudaGetSymbolAddress((void**)&pad, g_adst);
    cudaGetSymbolAddress((void**)&pahi, g_ahi);
    cudaGetSymbolAddress((void**)&palo, g_alo);
    cudaGetSymbolAddress((void**)&pbhi, g_bhi);
    cudaGetSymbolAddress((void**)&pblo, g_blo);

    cudaFuncSetAttribute(gemm_mma_kernel, cudaFuncAttributeMaxDynamicSharedMemorySize, GEMM_SMEM);

    // ---- CSR build ----
    zero_deg_kernel<<<div_up(NN, 256), 256>>>();
    hist_kernel<<<div_up(ET, 256), 256>>>(ei);
    scan_kernel<<<1, 1024>>>();
    cursor_kernel<<<div_up(NN, 256), 256>>>();
    scatter_kernel<<<div_up(ET, 256), 256>>>(ei);

    // pad rows for layers 1-4 A buffers
    zero_pad_kernel<<<div_up((NPAD - NN) * 800, 256), 256>>>();

    const int HEADS[5] = {4, 4, 4, 4, 1};
    const int FIN[5]   = {200, 800, 800, 800, 800};
    const int MT = NPAD / 64;   // 157 m-tiles

    for (int L = 0; L < 5; L++) {
        int H  = HEADS[L];
        int HC = H * CC;
        int K  = FIN[L];
        int Kp = (K + 31) & ~31;

        if (L == 0)
            prep_a_kernel<<<div_up(NPAD * Kp, 256), 256>>>(X, K, Kp);
        prep_b_kernel<<<div_up(H * NB * Kp, 256), 256>>>(W[L], K, Kp, H);

        dim3 ggrid(MT, H);
        gemm_mma_kernel<<<ggrid, 256, GEMM_SMEM>>>(
            pahi, palo, pbhi, pblo, ph, AS[L], AD[L], pas, pad, Kp, HC, H);

        // inner layers: float output is dead (next layer reads bf16 hi/lo) -> nullptr
        float* outp  = (L == 4) ? out_x : nullptr;
        float* attnp = (L == 4) ? out_a : nullptr;
        __nv_bfloat16* hi_o = (L < 4) ? pahi : nullptr;
        __nv_bfloat16* lo_o = (L < 4) ? palo : nullptr;
        agg_kernel<<<NN, 256>>>(ph, Bb[L], outp, attnp, hi_o, lo_o, H, HC);
    }
    (void)in_sizes; (void)n_in; (void)out_size;
}

// round 11
// speedup vs baseline: 2.2105x; 1.3217x over previous
#include <cuda_runtime.h>
#include <cuda_bf16.h>
#include <math.h>
#include <stdint.h>

// Problem constants
#define NN 10000      // nodes
#define NPAD 10048    // padded rows (multiple of 64)
#define EE 100000     // raw edges
#define ET 110000     // edges + self loops
#define CC 200        // channels per head
#define NB 224        // padded N per head

// ---------------- device scratch ----------------
__device__ __align__(16) float g_h[NN * 800];
__device__ __align__(256) __nv_bfloat16 g_ahi[NPAD * 800];
__device__ __align__(256) __nv_bfloat16 g_alo[NPAD * 800];
__device__ __align__(256) __nv_bfloat16 g_bhi[4 * NB * 800];
__device__ __align__(256) __nv_bfloat16 g_blo[4 * NB * 800];
__device__ float g_asrc[NN * 4];
__device__ float g_adst[NN * 4];
__device__ int   g_deg[NN];
__device__ int   g_rowptr[NN + 1];
__device__ int   g_cursor[NN];
__device__ int   g_srcs[ET];
__device__ int   g_eid[ET];

static inline int div_up(int a, int b) { return (a + b - 1) / b; }

// ================= PTX helpers (base ISA only) =================
__device__ __forceinline__ uint32_t smem_u32(const void* p) {
    uint32_t a;
    asm("{ .reg .u64 t; cvta.to.shared.u64 t, %1; cvt.u32.u64 %0, t; }" : "=r"(a) : "l"(p));
    return a;
}
#define CP_ASYNC16(dst, src) \
    asm volatile("cp.async.cg.shared.global [%0], [%1], 16;" :: "r"(dst), "l"(src))
#define CP_COMMIT asm volatile("cp.async.commit_group;" ::: "memory")
#define CP_WAIT1  asm volatile("cp.async.wait_group 1;" ::: "memory")
#define CP_WAIT0  asm volatile("cp.async.wait_group 0;" ::: "memory")

__device__ __forceinline__ void ldsm_x4(uint32_t* r, uint32_t addr) {
    asm volatile("ldmatrix.sync.aligned.m8n8.x4.shared.b16 {%0,%1,%2,%3}, [%4];"
        : "=r"(r[0]), "=r"(r[1]), "=r"(r[2]), "=r"(r[3]) : "r"(addr));
}
__device__ __forceinline__ void ldsm_x2(uint32_t* r, uint32_t addr) {
    asm volatile("ldmatrix.sync.aligned.m8n8.x2.shared.b16 {%0,%1}, [%2];"
        : "=r"(r[0]), "=r"(r[1]) : "r"(addr));
}
__device__ __forceinline__ void mma_bf16(float* d, const uint32_t* a, const uint32_t* b) {
    asm volatile("mma.sync.aligned.m16n8k16.row.col.f32.bf16.bf16.f32 "
        "{%0,%1,%2,%3}, {%4,%5,%6,%7}, {%8,%9}, {%0,%1,%2,%3};"
        : "+f"(d[0]), "+f"(d[1]), "+f"(d[2]), "+f"(d[3])
        : "r"(a[0]), "r"(a[1]), "r"(a[2]), "r"(a[3]), "r"(b[0]), "r"(b[1]));
}

// ---------------- CSR build ----------------
__global__ void zero_deg_kernel() {
    int i = blockIdx.x * blockDim.x + threadIdx.x;
    if (i < NN) g_deg[i] = 0;
}
__global__ void hist_kernel(const int* __restrict__ ei) {
    int e = blockIdx.x * blockDim.x + threadIdx.x;
    if (e >= ET) return;
    int d = (e < EE) ? ei[EE + e] : (e - EE);
    atomicAdd(&g_deg[d], 1);
}
__global__ void scan_kernel() {
    __shared__ int sh[1024];
    __shared__ int carry;
    int tid = threadIdx.x;
    if (tid == 0) carry = 0;
    __syncthreads();
    for (int base = 0; base < NN; base += 1024) {
        int i = base + tid;
        int v = (i < NN) ? g_deg[i] : 0;
        int x = v;
        #pragma unroll
        for (int off = 1; off < 1024; off <<= 1) {
            sh[tid] = x;
            __syncthreads();
            if (tid >= off) x += sh[tid - off];
            __syncthreads();
        }
        if (i < NN) g_rowptr[i] = carry + x - v;
        sh[tid] = x;
        __syncthreads();
        int total = sh[1023];
        __syncthreads();
        if (tid == 0) carry += total;
        __syncthreads();
    }
    if (threadIdx.x == 0) g_rowptr[NN] = carry;
}
__global__ void cursor_kernel() {
    int i = blockIdx.x * blockDim.x + threadIdx.x;
    if (i < NN) g_cursor[i] = g_rowptr[i];
}
__global__ void scatter_kernel(const int* __restrict__ ei) {
    int e = blockIdx.x * blockDim.x + threadIdx.x;
    if (e >= ET) return;
    int s, d;
    if (e < EE) { s = ei[e]; d = ei[EE + e]; }
    else        { s = e - EE; d = e - EE; }
    int pos = atomicAdd(&g_cursor[d], 1);
    g_srcs[pos] = s;
    g_eid[pos]  = e;
}

// ---------------- bf16 hi/lo prep ----------------
__device__ __forceinline__ void bf16_split(float v, __nv_bfloat16& h, __nv_bfloat16& l) {
    h = __float2bfloat16(v);
    l = __float2bfloat16(v - __bfloat162float(h));
}

// X -> g_ahi/g_alo (layer 0 only)
__global__ void prep_a_kernel(const float* __restrict__ A, int K, int Kp) {
    int idx = blockIdx.x * blockDim.x + threadIdx.x;
    if (idx >= NPAD * Kp) return;
    int row = idx / Kp;
    int k = idx - row * Kp;
    float v = (row < NN && k < K) ? A[(size_t)row * K + k] : 0.f;
    __nv_bfloat16 h, l;
    bf16_split(v, h, l);
    g_ahi[idx] = h;
    g_alo[idx] = l;
}

// zero the 48 pad rows at stride 800 (used by layers 1-4)
__global__ void zero_pad_kernel() {
    int idx = blockIdx.x * blockDim.x + threadIdx.x;
    int total = (NPAD - NN) * 800;
    if (idx >= total) return;
    int off = NN * 800 + idx;
    g_ahi[off] = __float2bfloat16(0.f);
    g_alo[off] = __float2bfloat16(0.f);
}

// W [K, HC] -> per-head transposed padded Bt [H][NB][Kp]
__global__ void prep_b_kernel(const float* __restrict__ W, int K, int Kp, int H) {
    int idx = blockIdx.x * blockDim.x + threadIdx.x;
    int total = H * NB * Kp;
    if (idx >= total) return;
    int h = idx / (NB * Kp);
    int rem = idx - h * NB * Kp;
    int n = rem / Kp;
    int k = rem - n * Kp;
    int HC = H * CC;
    float v = (n < CC && k < K) ? W[(size_t)k * HC + h * CC + n] : 0.f;
    __nv_bfloat16 hi, lo;
    bf16_split(v, hi, lo);
    g_bhi[idx] = hi;
    g_blo[idx] = lo;
}

// ================= mma.sync bf16-split GEMM =================
// 3-stage cp.async pipeline, ONE __syncthreads per K-iteration.
#define SA_LO 4096u
#define SB_HI 8192u
#define SB_LO 22528u
#define STAGE 36864u
#define NSTAGE 3
#define CSTRIDE 232
#define GEMM_SMEM (NSTAGE * 36864)

__device__ __forceinline__ uint32_t swz(int r, int c) {
    return (uint32_t)(r * 64 + ((c ^ ((r >> 1) & 3)) << 4));
}

__device__ __forceinline__ void fill_stage(
    uint32_t su, int buf, int k0,
    const __nv_bfloat16* __restrict__ ahi, const __nv_bfloat16* __restrict__ alo,
    const __nv_bfloat16* __restrict__ bh, const __nv_bfloat16* __restrict__ bl,
    int Kp, int row0, int tid)
{
    uint32_t sb = su + (uint32_t)buf * STAGE;
    {
        int r = tid >> 2, c = tid & 3;
        uint32_t da = sb + swz(r, c);
        const char* sa = (const char*)(ahi + (size_t)(row0 + r) * Kp + k0) + c * 16;
        CP_ASYNC16(da, sa);
        const char* sl = (const char*)(alo + (size_t)(row0 + r) * Kp + k0) + c * 16;
        CP_ASYNC16(da + SA_LO, sl);
    }
    #pragma unroll
    for (int j0 = 0; j0 < 896; j0 += 256) {
        int j = j0 + tid;
        if (j < 896) {
            int r = j >> 2, c = j & 3;
            uint32_t db = sb + SB_HI + swz(r, c);
            const char* sh = (const char*)(bh + (size_t)r * Kp + k0) + c * 16;
            CP_ASYNC16(db, sh);
            const char* sl = (const char*)(bl + (size_t)r * Kp + k0) + c * 16;
            CP_ASYNC16(db + (SB_LO - SB_HI), sl);
        }
    }
}

__global__ __launch_bounds__(256) void gemm_mma_kernel(
    const __nv_bfloat16* __restrict__ Ahi, const __nv_bfloat16* __restrict__ Alo,
    const __nv_bfloat16* __restrict__ Bhi, const __nv_bfloat16* __restrict__ Blo,
    float* __restrict__ C,
    const float* __restrict__ asv_g, const float* __restrict__ adv_g,
    float* __restrict__ asrc_o, float* __restrict__ adst_o,
    int Kp, int Ncol, int H)
{
    extern __shared__ char smem[];
    uint32_t su = smem_u32(smem);
    int tid = threadIdx.x;
    int w = tid >> 5, lane = tid & 31;
    int mw = w >> 2, nw = w & 3;
    int bm = blockIdx.x, bn = blockIdx.y;
    int row0 = bm * 64;

    const __nv_bfloat16* bhp = Bhi + (size_t)bn * NB * Kp;
    const __nv_bfloat16* blp = Blo + (size_t)bn * NB * Kp;

    float acc[2][7][4];
    #pragma unroll
    for (int mf = 0; mf < 2; mf++)
        #pragma unroll
        for (int nf = 0; nf < 7; nf++)
            #pragma unroll
            for (int q = 0; q < 4; q++) acc[mf][nf][q] = 0.f;

    int niter = Kp >> 5;
    // prologue: fill stages 0 and 1 (niter >= 7 always here)
    fill_stage(su, 0, 0, Ahi, Alo, bhp, blp, Kp, row0, tid);
    CP_COMMIT;
    fill_stage(su, 1, 32, Ahi, Alo, bhp, blp, Kp, row0, tid);
    CP_COMMIT;

    for (int i = 0; i < niter; i++) {
        CP_WAIT1;             // stage i arrived (stage i+1 may be in flight)
        __syncthreads();      // visibility + WAR protection for the fill below
        if (i + 2 < niter)
            fill_stage(su, (i + 2) % NSTAGE, (i + 2) * 32,
                       Ahi, Alo, bhp, blp, Kp, row0, tid);
        CP_COMMIT;            // always commit to keep group accounting uniform

        uint32_t sb = su + (uint32_t)(i % NSTAGE) * STAGE;
        #pragma unroll
        for (int kk = 0; kk < 2; kk++) {
            // ---- load all B frags for this kk (paired x4) ----
            uint32_t bh[7][2], bl[7][2];
            {
                int g = lane >> 3;
                #pragma unroll
                for (int p = 0; p < 3; p++) {
                    int nf = p * 2;
                    int r = nw * 56 + (nf + (g >> 1)) * 8 + (lane & 7);
                    int ch = 2 * kk + (g & 1);
                    uint32_t addr = sb + SB_HI + swz(r, ch);
                    uint32_t t[4];
                    ldsm_x4(t, addr);
                    bh[nf][0] = t[0]; bh[nf][1] = t[1];
                    bh[nf + 1][0] = t[2]; bh[nf + 1][1] = t[3];
                    ldsm_x4(t, addr + (SB_LO - SB_HI));
                    bl[nf][0] = t[0]; bl[nf][1] = t[1];
                    bl[nf + 1][0] = t[2]; bl[nf + 1][1] = t[3];
                }
                int r = nw * 56 + 48 + (lane & 7);
                int ch = 2 * kk + ((lane >> 3) & 1);
                uint32_t addr = sb + SB_HI + swz(r, ch);
                ldsm_x2(bh[6], addr);
                ldsm_x2(bl[6], addr + (SB_LO - SB_HI));
            }
            // ---- load A frags ----
            uint32_t ah[2][4], al[2][4];
            #pragma unroll
            for (int mf = 0; mf < 2; mf++) {
                int r = mw * 32 + mf * 16 + (lane & 7) + ((lane >> 3) & 1) * 8;
                int ch = 2 * kk + (lane >> 4);
                uint32_t addr = sb + swz(r, ch);
                ldsm_x4(ah[mf], addr);
                ldsm_x4(al[mf], addr + SA_LO);
            }
            // ---- three independent sweeps (14 independent MMAs each) ----
            #pragma unroll
            for (int nf = 0; nf < 7; nf++)
                #pragma unroll
                for (int mf = 0; mf < 2; mf++)
                    mma_bf16(acc[mf][nf], ah[mf], bh[nf]);
            #pragma unroll
            for (int nf = 0; nf < 7; nf++)
                #pragma unroll
                for (int mf = 0; mf < 2; mf++)
                    mma_bf16(acc[mf][nf], al[mf], bh[nf]);
            #pragma unroll
            for (int nf = 0; nf < 7; nf++)
                #pragma unroll
                for (int mf = 0; mf < 2; mf++)
                    mma_bf16(acc[mf][nf], ah[mf], bl[nf]);
        }
    }
    CP_WAIT0;
    __syncthreads();   // all cp.async done + all compute done before smem reuse

    // ---- epilogue: frags -> smem ----
    float* Cs = (float*)smem;
    #pragma unroll
    for (int mf = 0; mf < 2; mf++) {
        #pragma unroll
        for (int nf = 0; nf < 7; nf++) {
            int r0 = mw * 32 + mf * 16 + (lane >> 2);
            int cb = nw * 56 + nf * 8 + 2 * (lane & 3);
            *(float2*)&Cs[r0 * CSTRIDE + cb] = make_float2(acc[mf][nf][0], acc[mf][nf][1]);
            *(float2*)&Cs[(r0 + 8) * CSTRIDE + cb] = make_float2(acc[mf][nf][2], acc[mf][nf][3]);
        }
    }
    __syncthreads();

    // fused alpha dots: warp w handles rows w*8 .. w*8+7
    const float* asv = asv_g + bn * CC;
    const float* adv = adv_g + bn * CC;
    #pragma unroll
    for (int i = 0; i < 8; i++) {
        int r = w * 8 + i;
        int gr = row0 + r;
        float s1 = 0.f, s2 = 0.f;
        for (int c = lane; c < CC; c += 32) {
            float v = Cs[r * CSTRIDE + c];
            s1 += v * __ldg(asv + c);
            s2 += v * __ldg(adv + c);
        }
        #pragma unroll
        for (int o = 16; o; o >>= 1) {
            s1 += __shfl_xor_sync(0xffffffffu, s1, o);
            s2 += __shfl_xor_sync(0xffffffffu, s2, o);
        }
        if (lane == 0 && gr < NN) {
            asrc_o[gr * H + bn] = s1;
            adst_o[gr * H + bn] = s2;
        }
    }

    // coalesced store of the 200 real columns
    for (int idx = tid; idx < 64 * CC; idx += 256) {
        int r = idx / CC;
        int c = idx - r * CC;
        int gr = row0 + r;
        if (gr < NN)
            C[(size_t)gr * Ncol + bn * CC + c] = Cs[r * CSTRIDE + c];
    }
}

// ---------------- segment softmax + aggregation: one warp per (node, head) ----------------
// Pass A: online softmax (m, den) over incoming edges.
// Pass B: weighted accumulation of 200 channels (lane owns c = lane + 32k),
//         attn write (lane 0), bias + GELU + fused bf16 hi/lo split.
// No block barriers at all.
__global__ __launch_bounds__(256) void agg_warp_kernel(
    const float* __restrict__ hfeat, const float* __restrict__ bias,
    float* __restrict__ out, float* __restrict__ attn,
    __nv_bfloat16* __restrict__ ahi_o, __nv_bfloat16* __restrict__ alo_o,
    int H, int HC)
{
    int gw = (blockIdx.x * blockDim.x + threadIdx.x) >> 5;
    int lane = threadIdx.x & 31;
    if (gw >= NN * H) return;
    int n = gw / H;
    int h = gw - n * H;

    int start = g_rowptr[n];
    int end   = g_rowptr[n + 1];
    float adn = g_adst[n * H + h];

    // pass A: online (m, den)
    float m = -1e30f, den = 0.f;
    for (int j = start; j < end; j++) {
        int s = __ldg(&g_srcs[j]);
        float e = __ldg(&g_asrc[s * H + h]) + adn;
        e = (e > 0.f) ? e : 0.2f * e;
        float mn = fmaxf(m, e);
        den = den * expf(m - mn) + expf(e - mn);
        m = mn;
    }
    float invden = 1.f / den;

    // pass B: weighted accumulation
    float acc[7];
    #pragma unroll
    for (int k = 0; k < 7; k++) acc[k] = 0.f;

    for (int j = start; j < end; j++) {
        int s = __ldg(&g_srcs[j]);
        float e = __ldg(&g_asrc[s * H + h]) + adn;
        e = (e > 0.f) ? e : 0.2f * e;
        float wv = expf(e - m) * invden;
        if (attn && lane == 0) attn[__ldg(&g_eid[j])] = wv;
        const float* hp = hfeat + (size_t)s * HC + h * CC;
        #pragma unroll
        for (int k = 0; k < 7; k++) {
            int c = lane + 32 * k;
            if (c < CC) acc[k] += wv * __ldg(hp + c);
        }
    }

    // epilogue: bias + GELU + outputs
    const float kc = 0.70710678118654752f;
    #pragma unroll
    for (int k = 0; k < 7; k++) {
        int c = lane + 32 * k;
        if (c < CC) {
            float v = acc[k] + __ldg(&bias[h * CC + c]);
            v = 0.5f * v * (1.f + erff(v * kc));
            if (out) out[(size_t)n * HC + h * CC + c] = v;
            if (ahi_o) {
                size_t base = (size_t)n * 800 + h * CC + c;
                __nv_bfloat16 hi, lo;
                bf16_split(v, hi, lo);
                ahi_o[base] = hi;
                alo_o[base] = lo;
            }
        }
    }
}

// ---------------- host launch ----------------
extern "C" void kernel_launch(void* const* d_in, const int* in_sizes, int n_in,
                              void* d_out, int out_size)
{
    const float* X  = (const float*)d_in[0];
    const int*   ei = (const int*)d_in[1];
    const float *W[5], *AS[5], *AD[5], *Bb[5];
    for (int i = 0; i < 5; i++) {
        W[i]  = (const float*)d_in[2 + 4 * i];
        AS[i] = (const float*)d_in[3 + 4 * i];
        AD[i] = (const float*)d_in[4 + 4 * i];
        Bb[i] = (const float*)d_in[5 + 4 * i];
    }
    float* out_x = (float*)d_out;
    float* out_a = out_x + (size_t)NN * 200;

    float *ph, *pas, *pad;
    __nv_bfloat16 *pahi, *palo, *pbhi, *pblo;
    cudaGetSymbolAddress((void**)&ph,  g_h);
    cudaGetSymbolAddress((void**)&pas, g_asrc);
    cudaGetSymbolAddress((void**)&pad, g_adst);
    cudaGetSymbolAddress((void**)&pahi, g_ahi);
    cudaGetSymbolAddress((void**)&palo, g_alo);
    cudaGetSymbolAddress((void**)&pbhi, g_bhi);
    cudaGetSymbolAddress((void**)&pblo, g_blo);

    cudaFuncSetAttribute(gemm_mma_kernel, cudaFuncAttributeMaxDynamicSharedMemorySize, GEMM_SMEM);

    // ---- CSR build ----
    zero_deg_kernel<<<div_up(NN, 256), 256>>>();
    hist_kernel<<<div_up(ET, 256), 256>>>(ei);
    scan_kernel<<<1, 1024>>>();
    cursor_kernel<<<div_up(NN, 256), 256>>>();
    scatter_kernel<<<div_up(ET, 256), 256>>>(ei);

    // pad rows for layers 1-4 A buffers
    zero_pad_kernel<<<div_up((NPAD - NN) * 800, 256), 256>>>();

    const int HEADS[5] = {4, 4, 4, 4, 1};
    const int FIN[5]   = {200, 800, 800, 800, 800};
    const int MT = NPAD / 64;   // 157 m-tiles

    for (int L = 0; L < 5; L++) {
        int H  = HEADS[L];
        int HC = H * CC;
        int K  = FIN[L];
        int Kp = (K + 31) & ~31;

        if (L == 0)
            prep_a_kernel<<<div_up(NPAD * Kp, 256), 256>>>(X, K, Kp);
        prep_b_kernel<<<div_up(H * NB * Kp, 256), 256>>>(W[L], K, Kp, H);

        dim3 ggrid(MT, H);
        gemm_mma_kernel<<<ggrid, 256, GEMM_SMEM>>>(
            pahi, palo, pbhi, pblo, ph, AS[L], AD[L], pas, pad, Kp, HC, H);

        // inner layers: float output is dead (next layer reads bf16 hi/lo) -> nullptr
        float* outp  = (L == 4) ? out_x : nullptr;
        float* attnp = (L == 4) ? out_a : nullptr;
        __nv_bfloat16* hi_o = (L < 4) ? pahi : nullptr;
        __nv_bfloat16* lo_o = (L < 4) ? palo : nullptr;
        int nwarps = NN * H;
        agg_warp_kernel<<<div_up(nwarps * 32, 256), 256>>>(
            ph, Bb[L], outp, attnp, hi_o, lo_o, H, HC);
    }
    (void)in_sizes; (void)n_in; (void)out_size;
}

// round 12
// speedup vs baseline: 2.2794x; 1.0312x over previous
#include <cuda_runtime.h>
#include <cuda_bf16.h>
#include <math.h>
#include <stdint.h>

// Problem constants
#define NN 10000      // nodes
#define NPAD 10048    // padded rows (multiple of 64)
#define EE 100000     // raw edges
#define ET 110000     // edges + self loops
#define CC 200        // channels per head
#define NB 224        // padded N per head

// ---------------- device scratch ----------------
__device__ __align__(16) float g_h[NN * 800];
__device__ __align__(256) __nv_bfloat16 g_ahi[NPAD * 800];
__device__ __align__(256) __nv_bfloat16 g_alo[NPAD * 800];
__device__ __align__(256) __nv_bfloat16 g_bhi[4 * NB * 800];
__device__ __align__(256) __nv_bfloat16 g_blo[4 * NB * 800];
__device__ float g_asrc[NN * 4];
__device__ float g_adst[NN * 4];
__device__ int   g_deg[NN];
__device__ int   g_rowptr[NN + 1];
__device__ int   g_cursor[NN];
__device__ int   g_srcs[ET];
__device__ int   g_eid[ET];

static inline int div_up(int a, int b) { return (a + b - 1) / b; }

// ================= PTX helpers (base ISA only) =================
__device__ __forceinline__ uint32_t smem_u32(const void* p) {
    uint32_t a;
    asm("{ .reg .u64 t; cvta.to.shared.u64 t, %1; cvt.u32.u64 %0, t; }" : "=r"(a) : "l"(p));
    return a;
}
#define CP_ASYNC16(dst, src) \
    asm volatile("cp.async.cg.shared.global [%0], [%1], 16;" :: "r"(dst), "l"(src))
#define CP_COMMIT asm volatile("cp.async.commit_group;" ::: "memory")
#define CP_WAIT1  asm volatile("cp.async.wait_group 1;" ::: "memory")
#define CP_WAIT0  asm volatile("cp.async.wait_group 0;" ::: "memory")

__device__ __forceinline__ void ldsm_x4(uint32_t* r, uint32_t addr) {
    asm volatile("ldmatrix.sync.aligned.m8n8.x4.shared.b16 {%0,%1,%2,%3}, [%4];"
        : "=r"(r[0]), "=r"(r[1]), "=r"(r[2]), "=r"(r[3]) : "r"(addr));
}
__device__ __forceinline__ void ldsm_x2(uint32_t* r, uint32_t addr) {
    asm volatile("ldmatrix.sync.aligned.m8n8.x2.shared.b16 {%0,%1}, [%2];"
        : "=r"(r[0]), "=r"(r[1]) : "r"(addr));
}
__device__ __forceinline__ void mma_bf16(float* d, const uint32_t* a, const uint32_t* b) {
    asm volatile("mma.sync.aligned.m16n8k16.row.col.f32.bf16.bf16.f32 "
        "{%0,%1,%2,%3}, {%4,%5,%6,%7}, {%8,%9}, {%0,%1,%2,%3};"
        : "+f"(d[0]), "+f"(d[1]), "+f"(d[2]), "+f"(d[3])
        : "r"(a[0]), "r"(a[1]), "r"(a[2]), "r"(a[3]), "r"(b[0]), "r"(b[1]));
}

// ---------------- CSR build ----------------
__global__ void zero_deg_kernel() {
    int i = blockIdx.x * blockDim.x + threadIdx.x;
    if (i < NN) g_deg[i] = 0;
}
__global__ void hist_kernel(const int* __restrict__ ei) {
    int e = blockIdx.x * blockDim.x + threadIdx.x;
    if (e >= ET) return;
    int d = (e < EE) ? ei[EE + e] : (e - EE);
    atomicAdd(&g_deg[d], 1);
}
__global__ void scan_kernel() {
    __shared__ int sh[1024];
    __shared__ int carry;
    int tid = threadIdx.x;
    if (tid == 0) carry = 0;
    __syncthreads();
    for (int base = 0; base < NN; base += 1024) {
        int i = base + tid;
        int v = (i < NN) ? g_deg[i] : 0;
        int x = v;
        #pragma unroll
        for (int off = 1; off < 1024; off <<= 1) {
            sh[tid] = x;
            __syncthreads();
            if (tid >= off) x += sh[tid - off];
            __syncthreads();
        }
        if (i < NN) g_rowptr[i] = carry + x - v;
        sh[tid] = x;
        __syncthreads();
        int total = sh[1023];
        __syncthreads();
        if (tid == 0) carry += total;
        __syncthreads();
    }
    if (threadIdx.x == 0) g_rowptr[NN] = carry;
}
__global__ void cursor_kernel() {
    int i = blockIdx.x * blockDim.x + threadIdx.x;
    if (i < NN) g_cursor[i] = g_rowptr[i];
}
__global__ void scatter_kernel(const int* __restrict__ ei) {
    int e = blockIdx.x * blockDim.x + threadIdx.x;
    if (e >= ET) return;
    int s, d;
    if (e < EE) { s = ei[e]; d = ei[EE + e]; }
    else        { s = e - EE; d = e - EE; }
    int pos = atomicAdd(&g_cursor[d], 1);
    g_srcs[pos] = s;
    g_eid[pos]  = e;
}

// ---------------- bf16 hi/lo prep ----------------
__device__ __forceinline__ void bf16_split(float v, __nv_bfloat16& h, __nv_bfloat16& l) {
    h = __float2bfloat16(v);
    l = __float2bfloat16(v - __bfloat162float(h));
}

// X -> g_ahi/g_alo (layer 0 only)
__global__ void prep_a_kernel(const float* __restrict__ A, int K, int Kp) {
    int idx = blockIdx.x * blockDim.x + threadIdx.x;
    if (idx >= NPAD * Kp) return;
    int row = idx / Kp;
    int k = idx - row * Kp;
    float v = (row < NN && k < K) ? A[(size_t)row * K + k] : 0.f;
    __nv_bfloat16 h, l;
    bf16_split(v, h, l);
    g_ahi[idx] = h;
    g_alo[idx] = l;
}

// zero the 48 pad rows at stride 800 (used by layers 1-4)
__global__ void zero_pad_kernel() {
    int idx = blockIdx.x * blockDim.x + threadIdx.x;
    int total = (NPAD - NN) * 800;
    if (idx >= total) return;
    int off = NN * 800 + idx;
    g_ahi[off] = __float2bfloat16(0.f);
    g_alo[off] = __float2bfloat16(0.f);
}

// W [K, HC] -> per-head transposed padded Bt [H][NB][Kp]
__global__ void prep_b_kernel(const float* __restrict__ W, int K, int Kp, int H) {
    int idx = blockIdx.x * blockDim.x + threadIdx.x;
    int total = H * NB * Kp;
    if (idx >= total) return;
    int h = idx / (NB * Kp);
    int rem = idx - h * NB * Kp;
    int n = rem / Kp;
    int k = rem - n * Kp;
    int HC = H * CC;
    float v = (n < CC && k < K) ? W[(size_t)k * HC + h * CC + n] : 0.f;
    __nv_bfloat16 hi, lo;
    bf16_split(v, hi, lo);
    g_bhi[idx] = hi;
    g_blo[idx] = lo;
}

// ================= mma.sync bf16-split GEMM =================
// 3-stage cp.async pipeline, ONE __syncthreads per K-iteration.
// __launch_bounds__(256, 2): 2 CTAs/SM (smem 2x110.6KB fits in 228KB);
// bl reuses bh's registers to stay under the 128-reg cap.
#define SA_LO 4096u
#define SB_HI 8192u
#define SB_LO 22528u
#define STAGE 36864u
#define NSTAGE 3
#define CSTRIDE 232
#define GEMM_SMEM (NSTAGE * 36864)

__device__ __forceinline__ uint32_t swz(int r, int c) {
    return (uint32_t)(r * 64 + ((c ^ ((r >> 1) & 3)) << 4));
}

__device__ __forceinline__ void fill_stage(
    uint32_t su, int buf, int k0,
    const __nv_bfloat16* __restrict__ ahi, const __nv_bfloat16* __restrict__ alo,
    const __nv_bfloat16* __restrict__ bh, const __nv_bfloat16* __restrict__ bl,
    int Kp, int row0, int tid)
{
    uint32_t sb = su + (uint32_t)buf * STAGE;
    {
        int r = tid >> 2, c = tid & 3;
        uint32_t da = sb + swz(r, c);
        const char* sa = (const char*)(ahi + (size_t)(row0 + r) * Kp + k0) + c * 16;
        CP_ASYNC16(da, sa);
        const char* sl = (const char*)(alo + (size_t)(row0 + r) * Kp + k0) + c * 16;
        CP_ASYNC16(da + SA_LO, sl);
    }
    #pragma unroll
    for (int j0 = 0; j0 < 896; j0 += 256) {
        int j = j0 + tid;
        if (j < 896) {
            int r = j >> 2, c = j & 3;
            uint32_t db = sb + SB_HI + swz(r, c);
            const char* sh = (const char*)(bh + (size_t)r * Kp + k0) + c * 16;
            CP_ASYNC16(db, sh);
            const char* sl = (const char*)(bl + (size_t)r * Kp + k0) + c * 16;
            CP_ASYNC16(db + (SB_LO - SB_HI), sl);
        }
    }
}

// load the 7 B n-frags (hi or lo plane selected by `plane_off`) for one kk
__device__ __forceinline__ void load_b_frags(
    uint32_t bb[7][2], uint32_t sb, uint32_t plane_off, int kk, int nw, int lane)
{
    int g = lane >> 3;
    #pragma unroll
    for (int p = 0; p < 3; p++) {
        int nf = p * 2;
        int r = nw * 56 + (nf + (g >> 1)) * 8 + (lane & 7);
        int ch = 2 * kk + (g & 1);
        uint32_t addr = sb + SB_HI + plane_off + swz(r, ch);
        uint32_t t[4];
        ldsm_x4(t, addr);
        bb[nf][0] = t[0]; bb[nf][1] = t[1];
        bb[nf + 1][0] = t[2]; bb[nf + 1][1] = t[3];
    }
    int r = nw * 56 + 48 + (lane & 7);
    int ch = 2 * kk + ((lane >> 3) & 1);
    ldsm_x2(bb[6], sb + SB_HI + plane_off + swz(r, ch));
}

__global__ __launch_bounds__(256, 2) void gemm_mma_kernel(
    const __nv_bfloat16* __restrict__ Ahi, const __nv_bfloat16* __restrict__ Alo,
    const __nv_bfloat16* __restrict__ Bhi, const __nv_bfloat16* __restrict__ Blo,
    float* __restrict__ C,
    const float* __restrict__ asv_g, const float* __restrict__ adv_g,
    float* __restrict__ asrc_o, float* __restrict__ adst_o,
    int Kp, int Ncol, int H)
{
    extern __shared__ char smem[];
    uint32_t su = smem_u32(smem);
    int tid = threadIdx.x;
    int w = tid >> 5, lane = tid & 31;
    int mw = w >> 2, nw = w & 3;
    int bm = blockIdx.x, bn = blockIdx.y;
    int row0 = bm * 64;

    const __nv_bfloat16* bhp = Bhi + (size_t)bn * NB * Kp;
    const __nv_bfloat16* blp = Blo + (size_t)bn * NB * Kp;

    float acc[2][7][4];
    #pragma unroll
    for (int mf = 0; mf < 2; mf++)
        #pragma unroll
        for (int nf = 0; nf < 7; nf++)
            #pragma unroll
            for (int q = 0; q < 4; q++) acc[mf][nf][q] = 0.f;

    int niter = Kp >> 5;
    fill_stage(su, 0, 0, Ahi, Alo, bhp, blp, Kp, row0, tid);
    CP_COMMIT;
    fill_stage(su, 1, 32, Ahi, Alo, bhp, blp, Kp, row0, tid);
    CP_COMMIT;

    for (int i = 0; i < niter; i++) {
        CP_WAIT1;
        __syncthreads();
        if (i + 2 < niter)
            fill_stage(su, (i + 2) % NSTAGE, (i + 2) * 32,
                       Ahi, Alo, bhp, blp, Kp, row0, tid);
        CP_COMMIT;

        uint32_t sb = su + (uint32_t)(i % NSTAGE) * STAGE;
        #pragma unroll
        for (int kk = 0; kk < 2; kk++) {
            // A frags (hi + lo)
            uint32_t ah[2][4], al[2][4];
            #pragma unroll
            for (int mf = 0; mf < 2; mf++) {
                int r = mw * 32 + mf * 16 + (lane & 7) + ((lane >> 3) & 1) * 8;
                int ch = 2 * kk + (lane >> 4);
                uint32_t addr = sb + swz(r, ch);
                ldsm_x4(ah[mf], addr);
                ldsm_x4(al[mf], addr + SA_LO);
            }
            // B hi frags -> sweep1 (ah*bh), sweep2 (al*bh)
            uint32_t bb[7][2];
            load_b_frags(bb, sb, 0u, kk, nw, lane);
            #pragma unroll
            for (int nf = 0; nf < 7; nf++)
                #pragma unroll
                for (int mf = 0; mf < 2; mf++)
                    mma_bf16(acc[mf][nf], ah[mf], bb[nf]);
            #pragma unroll
            for (int nf = 0; nf < 7; nf++)
                #pragma unroll
                for (int mf = 0; mf < 2; mf++)
                    mma_bf16(acc[mf][nf], al[mf], bb[nf]);
            // B lo frags overwrite bb -> sweep3 (ah*bl)
            load_b_frags(bb, sb, SB_LO - SB_HI, kk, nw, lane);
            #pragma unroll
            for (int nf = 0; nf < 7; nf++)
                #pragma unroll
                for (int mf = 0; mf < 2; mf++)
                    mma_bf16(acc[mf][nf], ah[mf], bb[nf]);
        }
    }
    CP_WAIT0;
    __syncthreads();

    // ---- epilogue: frags -> smem ----
    float* Cs = (float*)smem;
    #pragma unroll
    for (int mf = 0; mf < 2; mf++) {
        #pragma unroll
        for (int nf = 0; nf < 7; nf++) {
            int r0 = mw * 32 + mf * 16 + (lane >> 2);
            int cb = nw * 56 + nf * 8 + 2 * (lane & 3);
            *(float2*)&Cs[r0 * CSTRIDE + cb] = make_float2(acc[mf][nf][0], acc[mf][nf][1]);
            *(float2*)&Cs[(r0 + 8) * CSTRIDE + cb] = make_float2(acc[mf][nf][2], acc[mf][nf][3]);
        }
    }
    __syncthreads();

    // fused alpha dots
    const float* asv = asv_g + bn * CC;
    const float* adv = adv_g + bn * CC;
    #pragma unroll
    for (int i = 0; i < 8; i++) {
        int r = w * 8 + i;
        int gr = row0 + r;
        float s1 = 0.f, s2 = 0.f;
        for (int c = lane; c < CC; c += 32) {
            float v = Cs[r * CSTRIDE + c];
            s1 += v * __ldg(asv + c);
            s2 += v * __ldg(adv + c);
        }
        #pragma unroll
        for (int o = 16; o; o >>= 1) {
            s1 += __shfl_xor_sync(0xffffffffu, s1, o);
            s2 += __shfl_xor_sync(0xffffffffu, s2, o);
        }
        if (lane == 0 && gr < NN) {
            asrc_o[gr * H + bn] = s1;
            adst_o[gr * H + bn] = s2;
        }
    }

    // coalesced store of the 200 real columns
    for (int idx = tid; idx < 64 * CC; idx += 256) {
        int r = idx / CC;
        int c = idx - r * CC;
        int gr = row0 + r;
        if (gr < NN)
            C[(size_t)gr * Ncol + bn * CC + c] = Cs[r * CSTRIDE + c];
    }
}

// ---------------- segment softmax + aggregation: one warp per (node, head) ----------------
__global__ __launch_bounds__(256) void agg_warp_kernel(
    const float* __restrict__ hfeat, const float* __restrict__ bias,
    float* __restrict__ out, float* __restrict__ attn,
    __nv_bfloat16* __restrict__ ahi_o, __nv_bfloat16* __restrict__ alo_o,
    int H, int HC)
{
    int gw = (blockIdx.x * blockDim.x + threadIdx.x) >> 5;
    int lane = threadIdx.x & 31;
    if (gw >= NN * H) return;
    int n = gw / H;
    int h = gw - n * H;

    int start = g_rowptr[n];
    int end   = g_rowptr[n + 1];
    float adn = g_adst[n * H + h];

    // pass A: online (m, den)
    float m = -1e30f, den = 0.f;
    for (int j = start; j < end; j++) {
        int s = __ldg(&g_srcs[j]);
        float e = __ldg(&g_asrc[s * H + h]) + adn;
        e = (e > 0.f) ? e : 0.2f * e;
        float mn = fmaxf(m, e);
        den = den * expf(m - mn) + expf(e - mn);
        m = mn;
    }
    float invden = 1.f / den;

    // pass B: weighted accumulation
    float acc[7];
    #pragma unroll
    for (int k = 0; k < 7; k++) acc[k] = 0.f;

    for (int j = start; j < end; j++) {
        int s = __ldg(&g_srcs[j]);
        float e = __ldg(&g_asrc[s * H + h]) + adn;
        e = (e > 0.f) ? e : 0.2f * e;
        float wv = expf(e - m) * invden;
        if (attn && lane == 0) attn[__ldg(&g_eid[j])] = wv;
        const float* hp = hfeat + (size_t)s * HC + h * CC;
        #pragma unroll
        for (int k = 0; k < 7; k++) {
            int c = lane + 32 * k;
            if (c < CC) acc[k] += wv * __ldg(hp + c);
        }
    }

    // epilogue: bias + GELU + outputs
    const float kc = 0.70710678118654752f;
    #pragma unroll
    for (int k = 0; k < 7; k++) {
        int c = lane + 32 * k;
        if (c < CC) {
            float v = acc[k] + __ldg(&bias[h * CC + c]);
            v = 0.5f * v * (1.f + erff(v * kc));
            if (out) out[(size_t)n * HC + h * CC + c] = v;
            if (ahi_o) {
                size_t base = (size_t)n * 800 + h * CC + c;
                __nv_bfloat16 hi, lo;
                bf16_split(v, hi, lo);
                ahi_o[base] = hi;
                alo_o[base] = lo;
            }
        }
    }
}

// ---------------- host launch ----------------
extern "C" void kernel_launch(void* const* d_in, const int* in_sizes, int n_in,
                              void* d_out, int out_size)
{
    const float* X  = (const float*)d_in[0];
    const int*   ei = (const int*)d_in[1];
    const float *W[5], *AS[5], *AD[5], *Bb[5];
    for (int i = 0; i < 5; i++) {
        W[i]  = (const float*)d_in[2 + 4 * i];
        AS[i] = (const float*)d_in[3 + 4 * i];
        AD[i] = (const float*)d_in[4 + 4 * i];
        Bb[i] = (const float*)d_in[5 + 4 * i];
    }
    float* out_x = (float*)d_out;
    float* out_a = out_x + (size_t)NN * 200;

    float *ph, *pas, *pad;
    __nv_bfloat16 *pahi, *palo, *pbhi, *pblo;
    cudaGetSymbolAddress((void**)&ph,  g_h);
    cudaGetSymbolAddress((void**)&pas, g_asrc);
    cudaGetSymbolAddress((void**)&pad, g_adst);
    cudaGetSymbolAddress((void**)&pahi, g_ahi);
    cudaGetSymbolAddress((void**)&palo, g_alo);
    cudaGetSymbolAddress((void**)&pbhi, g_bhi);
    cudaGetSymbolAddress((void**)&pblo, g_blo);

    cudaFuncSetAttribute(gemm_mma_kernel, cudaFuncAttributeMaxDynamicSharedMemorySize, GEMM_SMEM);

    // ---- CSR build ----
    zero_deg_kernel<<<div_up(NN, 256), 256>>>();
    hist_kernel<<<div_up(ET, 256), 256>>>(ei);
    scan_kernel<<<1, 1024>>>();
    cursor_kernel<<<div_up(NN, 256), 256>>>();
    scatter_kernel<<<div_up(ET, 256), 256>>>(ei);

    // pad rows for layers 1-4 A buffers
    zero_pad_kernel<<<div_up((NPAD - NN) * 800, 256), 256>>>();

    const int HEADS[5] = {4, 4, 4, 4, 1};
    const int FIN[5]   = {200, 800, 800, 800, 800};
    const int MT = NPAD / 64;   // 157 m-tiles

    for (int L = 0; L < 5; L++) {
        int H  = HEADS[L];
        int HC = H * CC;
        int K  = FIN[L];
        int Kp = (K + 31) & ~31;

        if (L == 0)
            prep_a_kernel<<<div_up(NPAD * Kp, 256), 256>>>(X, K, Kp);
        prep_b_kernel<<<div_up(H * NB * Kp, 256), 256>>>(W[L], K, Kp, H);

        dim3 ggrid(MT, H);
        gemm_mma_kernel<<<ggrid, 256, GEMM_SMEM>>>(
            pahi, palo, pbhi, pblo, ph, AS[L], AD[L], pas, pad, Kp, HC, H);

        float* outp  = (L == 4) ? out_x : nullptr;
        float* attnp = (L == 4) ? out_a : nullptr;
        __nv_bfloat16* hi_o = (L < 4) ? pahi : nullptr;
        __nv_bfloat16* lo_o = (L < 4) ? palo : nullptr;
        int nwarps = NN * H;
        agg_warp_kernel<<<div_up(nwarps * 32, 256), 256>>>(
            ph, Bb[L], outp, attnp, hi_o, lo_o, H, HC);
    }
    (void)in_sizes; (void)n_in; (void)out_size;
}

// round 13
// speedup vs baseline: 2.3844x; 1.0460x over previous
#include <cuda_runtime.h>
#include <cuda_bf16.h>
#include <math.h>
#include <stdint.h>

// Problem constants
#define NN 10000      // nodes
#define NPAD 10112    // padded rows (multiple of 128)
#define EE 100000     // raw edges
#define ET 110000     // edges + self loops
#define CC 200        // channels per head

// ---------------- device scratch ----------------
__device__ __align__(16) float g_h[NN * 800];
__device__ __align__(256) __nv_bfloat16 g_ahi[NPAD * 800];
__device__ __align__(256) __nv_bfloat16 g_alo[NPAD * 800];
__device__ __align__(256) __nv_bfloat16 g_bhi[800 * 800];
__device__ __align__(256) __nv_bfloat16 g_blo[800 * 800];
__device__ float g_asrc[NN * 4];
__device__ float g_adst[NN * 4];
__device__ int   g_deg[NN];
__device__ int   g_rowptr[NN + 1];
__device__ int   g_cursor[NN];
__device__ int   g_srcs[ET];
__device__ int   g_eid[ET];

static inline int div_up(int a, int b) { return (a + b - 1) / b; }

// ================= PTX helpers (base ISA only) =================
__device__ __forceinline__ uint32_t smem_u32(const void* p) {
    uint32_t a;
    asm("{ .reg .u64 t; cvta.to.shared.u64 t, %1; cvt.u32.u64 %0, t; }" : "=r"(a) : "l"(p));
    return a;
}
#define CP_ASYNC16(dst, src) \
    asm volatile("cp.async.cg.shared.global [%0], [%1], 16;" :: "r"(dst), "l"(src))
#define CP_COMMIT asm volatile("cp.async.commit_group;" ::: "memory")
#define CP_WAIT1  asm volatile("cp.async.wait_group 1;" ::: "memory")
#define CP_WAIT0  asm volatile("cp.async.wait_group 0;" ::: "memory")

__device__ __forceinline__ void ldsm_x4(uint32_t* r, uint32_t addr) {
    asm volatile("ldmatrix.sync.aligned.m8n8.x4.shared.b16 {%0,%1,%2,%3}, [%4];"
        : "=r"(r[0]), "=r"(r[1]), "=r"(r[2]), "=r"(r[3]) : "r"(addr));
}
__device__ __forceinline__ void ldsm_x2(uint32_t* r, uint32_t addr) {
    asm volatile("ldmatrix.sync.aligned.m8n8.x2.shared.b16 {%0,%1}, [%2];"
        : "=r"(r[0]), "=r"(r[1]) : "r"(addr));
}
__device__ __forceinline__ void mma_bf16(float* d, const uint32_t* a, const uint32_t* b) {
    asm volatile("mma.sync.aligned.m16n8k16.row.col.f32.bf16.bf16.f32 "
        "{%0,%1,%2,%3}, {%4,%5,%6,%7}, {%8,%9}, {%0,%1,%2,%3};"
        : "+f"(d[0]), "+f"(d[1]), "+f"(d[2]), "+f"(d[3])
        : "r"(a[0]), "r"(a[1]), "r"(a[2]), "r"(a[3]), "r"(b[0]), "r"(b[1]));
}

// ---------------- CSR build ----------------
__global__ void zero_deg_kernel() {
    int i = blockIdx.x * blockDim.x + threadIdx.x;
    if (i < NN) g_deg[i] = 0;
}
__global__ void hist_kernel(const int* __restrict__ ei) {
    int e = blockIdx.x * blockDim.x + threadIdx.x;
    if (e >= ET) return;
    int d = (e < EE) ? ei[EE + e] : (e - EE);
    atomicAdd(&g_deg[d], 1);
}
__global__ void scan_kernel() {
    __shared__ int sh[1024];
    __shared__ int carry;
    int tid = threadIdx.x;
    if (tid == 0) carry = 0;
    __syncthreads();
    for (int base = 0; base < NN; base += 1024) {
        int i = base + tid;
        int v = (i < NN) ? g_deg[i] : 0;
        int x = v;
        #pragma unroll
        for (int off = 1; off < 1024; off <<= 1) {
            sh[tid] = x;
            __syncthreads();
            if (tid >= off) x += sh[tid - off];
            __syncthreads();
        }
        if (i < NN) g_rowptr[i] = carry + x - v;
        sh[tid] = x;
        __syncthreads();
        int total = sh[1023];
        __syncthreads();
        if (tid == 0) carry += total;
        __syncthreads();
    }
    if (threadIdx.x == 0) g_rowptr[NN] = carry;
}
__global__ void cursor_kernel() {
    int i = blockIdx.x * blockDim.x + threadIdx.x;
    if (i < NN) g_cursor[i] = g_rowptr[i];
}
__global__ void scatter_kernel(const int* __restrict__ ei) {
    int e = blockIdx.x * blockDim.x + threadIdx.x;
    if (e >= ET) return;
    int s, d;
    if (e < EE) { s = ei[e]; d = ei[EE + e]; }
    else        { s = e - EE; d = e - EE; }
    int pos = atomicAdd(&g_cursor[d], 1);
    g_srcs[pos] = s;
    g_eid[pos]  = e;
}

// ---------------- bf16 hi/lo prep ----------------
__device__ __forceinline__ void bf16_split(float v, __nv_bfloat16& h, __nv_bfloat16& l) {
    h = __float2bfloat16(v);
    l = __float2bfloat16(v - __bfloat162float(h));
}

// X -> g_ahi/g_alo (layer 0 only)
__global__ void prep_a_kernel(const float* __restrict__ A, int K, int Kp) {
    int idx = blockIdx.x * blockDim.x + threadIdx.x;
    if (idx >= NPAD * Kp) return;
    int row = idx / Kp;
    int k = idx - row * Kp;
    float v = (row < NN && k < K) ? A[(size_t)row * K + k] : 0.f;
    __nv_bfloat16 h, l;
    bf16_split(v, h, l);
    g_ahi[idx] = h;
    g_alo[idx] = l;
}

// zero the pad rows at stride 800 (used by layers 1-4)
__global__ void zero_pad_kernel() {
    int idx = blockIdx.x * blockDim.x + threadIdx.x;
    int total = (NPAD - NN) * 800;
    if (idx >= total) return;
    int off = NN * 800 + idx;
    g_ahi[off] = __float2bfloat16(0.f);
    g_alo[off] = __float2bfloat16(0.f);
}

// W [K, HC] -> transposed Bt [NBT][Kp]; rows >= HC zero (L4 pad)
__global__ void prep_b_kernel(const float* __restrict__ W, int K, int Kp, int HC, int NBT) {
    int idx = blockIdx.x * blockDim.x + threadIdx.x;
    int total = NBT * Kp;
    if (idx >= total) return;
    int n = idx / Kp;
    int k = idx - n * Kp;
    float v = (n < HC && k < K) ? W[(size_t)k * HC + n] : 0.f;
    __nv_bfloat16 hi, lo;
    bf16_split(v, hi, lo);
    g_bhi[idx] = hi;
    g_blo[idx] = lo;
}

// zero alpha accumulators before each GEMM (atomicAdd targets)
__global__ void zero_alpha_kernel(int total) {
    int i = blockIdx.x * blockDim.x + threadIdx.x;
    if (i < total) { g_asrc[i] = 0.f; g_adst[i] = 0.f; }
}

// ================= mma.sync bf16-split GEMM =================
// Block tile 128(M) x 80(N), 8 warps = 4m x 2n, warp tile 32x40.
// 3-stage cp.async pipeline, one __syncthreads per K-iteration.
// Alpha dots computed per block with head-split buckets + atomicAdd.
#define SA_LO 8192u
#define SB_HI 16384u
#define SB_LO 21504u
#define STAGE 26624u
#define NSTAGE 3
#define CSTRIDE 88
#define GEMM_SMEM (NSTAGE * 26624)

__device__ __forceinline__ uint32_t swz(int r, int c) {
    return (uint32_t)(r * 64 + ((c ^ ((r >> 1) & 3)) << 4));
}

__device__ __forceinline__ void fill_stage(
    uint32_t su, int buf, int k0,
    const __nv_bfloat16* __restrict__ ahi, const __nv_bfloat16* __restrict__ alo,
    const __nv_bfloat16* __restrict__ bh, const __nv_bfloat16* __restrict__ bl,
    int Kp, int row0, int tid)
{
    uint32_t sb = su + (uint32_t)buf * STAGE;
    // A: 128 rows x 32 k = 512 16B-chunks per plane; 2 per thread
    #pragma unroll
    for (int it = 0; it < 2; it++) {
        int j = tid + it * 256;
        int r = j >> 2, c = j & 3;
        uint32_t da = sb + swz(r, c);
        const char* sa = (const char*)(ahi + (size_t)(row0 + r) * Kp + k0) + c * 16;
        CP_ASYNC16(da, sa);
        const char* sl = (const char*)(alo + (size_t)(row0 + r) * Kp + k0) + c * 16;
        CP_ASYNC16(da + SA_LO, sl);
    }
    // B: 80 rows x 32 k = 320 chunks per plane
    #pragma unroll
    for (int j0 = 0; j0 < 320; j0 += 256) {
        int j = j0 + tid;
        if (j < 320) {
            int r = j >> 2, c = j & 3;
            uint32_t db = sb + SB_HI + swz(r, c);
            const char* sh = (const char*)(bh + (size_t)r * Kp + k0) + c * 16;
            CP_ASYNC16(db, sh);
            const char* sl = (const char*)(bl + (size_t)r * Kp + k0) + c * 16;
            CP_ASYNC16(db + (SB_LO - SB_HI), sl);
        }
    }
}

// load the 5 B n-frags (hi or lo plane) for one kk
__device__ __forceinline__ void load_b_frags(
    uint32_t bb[5][2], uint32_t sb, uint32_t plane_off, int kk, int nw, int lane)
{
    int g = lane >> 3;
    #pragma unroll
    for (int p = 0; p < 2; p++) {
        int nf = p * 2;
        int r = nw * 40 + (nf + (g >> 1)) * 8 + (lane & 7);
        int ch = 2 * kk + (g & 1);
        uint32_t addr = sb + SB_HI + plane_off + swz(r, ch);
        uint32_t t[4];
        ldsm_x4(t, addr);
        bb[nf][0] = t[0]; bb[nf][1] = t[1];
        bb[nf + 1][0] = t[2]; bb[nf + 1][1] = t[3];
    }
    int r = nw * 40 + 32 + (lane & 7);
    int ch = 2 * kk + ((lane >> 3) & 1);
    ldsm_x2(bb[4], sb + SB_HI + plane_off + swz(r, ch));
}

__global__ __launch_bounds__(256, 2) void gemm_mma_kernel(
    const __nv_bfloat16* __restrict__ Ahi, const __nv_bfloat16* __restrict__ Alo,
    const __nv_bfloat16* __restrict__ Bhi, const __nv_bfloat16* __restrict__ Blo,
    float* __restrict__ C,
    const float* __restrict__ asv_g, const float* __restrict__ adv_g,
    float* __restrict__ asrc_o, float* __restrict__ adst_o,
    int Kp, int HC, int H)
{
    extern __shared__ char smem[];
    uint32_t su = smem_u32(smem);
    int tid = threadIdx.x;
    int w = tid >> 5, lane = tid & 31;
    int mw = w >> 1, nw = w & 1;
    int bm = blockIdx.x, bn = blockIdx.y;
    int row0 = bm * 128;
    int col0 = bn * 80;

    const __nv_bfloat16* bhp = Bhi + (size_t)col0 * Kp;
    const __nv_bfloat16* blp = Blo + (size_t)col0 * Kp;

    float acc[2][5][4];
    #pragma unroll
    for (int mf = 0; mf < 2; mf++)
        #pragma unroll
        for (int nf = 0; nf < 5; nf++)
            #pragma unroll
            for (int q = 0; q < 4; q++) acc[mf][nf][q] = 0.f;

    int niter = Kp >> 5;
    fill_stage(su, 0, 0, Ahi, Alo, bhp, blp, Kp, row0, tid);
    CP_COMMIT;
    fill_stage(su, 1, 32, Ahi, Alo, bhp, blp, Kp, row0, tid);
    CP_COMMIT;

    for (int i = 0; i < niter; i++) {
        CP_WAIT1;
        __syncthreads();
        if (i + 2 < niter)
            fill_stage(su, (i + 2) % NSTAGE, (i + 2) * 32,
                       Ahi, Alo, bhp, blp, Kp, row0, tid);
        CP_COMMIT;

        uint32_t sb = su + (uint32_t)(i % NSTAGE) * STAGE;
        #pragma unroll
        for (int kk = 0; kk < 2; kk++) {
            // A frags (hi + lo)
            uint32_t ah[2][4], al[2][4];
            #pragma unroll
            for (int mf = 0; mf < 2; mf++) {
                int r = mw * 32 + mf * 16 + (lane & 7) + ((lane >> 3) & 1) * 8;
                int ch = 2 * kk + (lane >> 4);
                uint32_t addr = sb + swz(r, ch);
                ldsm_x4(ah[mf], addr);
                ldsm_x4(al[mf], addr + SA_LO);
            }
            // B hi frags -> sweep1 (ah*bh), sweep2 (al*bh)
            uint32_t bb[5][2];
            load_b_frags(bb, sb, 0u, kk, nw, lane);
            #pragma unroll
            for (int nf = 0; nf < 5; nf++)
                #pragma unroll
                for (int mf = 0; mf < 2; mf++)
                    mma_bf16(acc[mf][nf], ah[mf], bb[nf]);
            #pragma unroll
            for (int nf = 0; nf < 5; nf++)
                #pragma unroll
                for (int mf = 0; mf < 2; mf++)
                    mma_bf16(acc[mf][nf], al[mf], bb[nf]);
            // B lo frags overwrite bb -> sweep3 (ah*bl)
            load_b_frags(bb, sb, SB_LO - SB_HI, kk, nw, lane);
            #pragma unroll
            for (int nf = 0; nf < 5; nf++)
                #pragma unroll
                for (int mf = 0; mf < 2; mf++)
                    mma_bf16(acc[mf][nf], ah[mf], bb[nf]);
        }
    }
    CP_WAIT0;
    __syncthreads();

    // ---- epilogue: frags -> smem ----
    float* Cs = (float*)smem;
    #pragma unroll
    for (int mf = 0; mf < 2; mf++) {
        #pragma unroll
        for (int nf = 0; nf < 5; nf++) {
            int r0 = mw * 32 + mf * 16 + (lane >> 2);
            int cb = nw * 40 + nf * 8 + 2 * (lane & 3);
            *(float2*)&Cs[r0 * CSTRIDE + cb] = make_float2(acc[mf][nf][0], acc[mf][nf][1]);
            *(float2*)&Cs[(r0 + 8) * CSTRIDE + cb] = make_float2(acc[mf][nf][2], acc[mf][nf][3]);
        }
    }
    __syncthreads();

    // alpha dots with head-split buckets; warp w handles rows w*16..w*16+15
    int h0 = col0 / CC;
    int hb = (h0 + 1) * CC - col0;   // local cols >= hb belong to head h0+1
    #pragma unroll
    for (int i = 0; i < 16; i++) {
        int r = w * 16 + i;
        int gr = row0 + r;
        float sa0 = 0.f, sa1 = 0.f, sd0 = 0.f, sd1 = 0.f;
        #pragma unroll
        for (int cc = 0; cc < 3; cc++) {
            int c = lane + cc * 32;
            int gc = col0 + c;
            if (c < 80 && gc < HC) {
                float v = Cs[r * CSTRIDE + c];
                float pa = v * __ldg(asv_g + gc);
                float pd = v * __ldg(adv_g + gc);
                if (c < hb) { sa0 += pa; sd0 += pd; }
                else        { sa1 += pa; sd1 += pd; }
            }
        }
        #pragma unroll
        for (int o = 16; o; o >>= 1) {
            sa0 += __shfl_xor_sync(0xffffffffu, sa0, o);
            sa1 += __shfl_xor_sync(0xffffffffu, sa1, o);
            sd0 += __shfl_xor_sync(0xffffffffu, sd0, o);
            sd1 += __shfl_xor_sync(0xffffffffu, sd1, o);
        }
        if (lane == 0 && gr < NN) {
            atomicAdd(&asrc_o[gr * H + h0], sa0);
            atomicAdd(&adst_o[gr * H + h0], sd0);
            if (hb < 80 && h0 + 1 < H) {
                atomicAdd(&asrc_o[gr * H + h0 + 1], sa1);
                atomicAdd(&adst_o[gr * H + h0 + 1], sd1);
            }
        }
    }

    // coalesced store of real columns
    for (int idx = tid; idx < 128 * 80; idx += 256) {
        int r = idx / 80;
        int c = idx - r * 80;
        int gr = row0 + r;
        int gc = col0 + c;
        if (gr < NN && gc < HC)
            C[(size_t)gr * HC + gc] = Cs[r * CSTRIDE + c];
    }
}

// ---------------- segment softmax + aggregation: one warp per (node, head) ----------------
__global__ __launch_bounds__(256) void agg_warp_kernel(
    const float* __restrict__ hfeat, const float* __restrict__ bias,
    float* __restrict__ out, float* __restrict__ attn,
    __nv_bfloat16* __restrict__ ahi_o, __nv_bfloat16* __restrict__ alo_o,
    int H, int HC)
{
    int gw = (blockIdx.x * blockDim.x + threadIdx.x) >> 5;
    int lane = threadIdx.x & 31;
    if (gw >= NN * H) return;
    int n = gw / H;
    int h = gw - n * H;

    int start = g_rowptr[n];
    int end   = g_rowptr[n + 1];
    float adn = g_adst[n * H + h];

    // pass A: online (m, den)
    float m = -1e30f, den = 0.f;
    for (int j = start; j < end; j++) {
        int s = __ldg(&g_srcs[j]);
        float e = __ldg(&g_asrc[s * H + h]) + adn;
        e = (e > 0.f) ? e : 0.2f * e;
        float mn = fmaxf(m, e);
        den = den * expf(m - mn) + expf(e - mn);
        m = mn;
    }
    float invden = 1.f / den;

    // pass B: weighted accumulation
    float acc[7];
    #pragma unroll
    for (int k = 0; k < 7; k++) acc[k] = 0.f;

    for (int j = start; j < end; j++) {
        int s = __ldg(&g_srcs[j]);
        float e = __ldg(&g_asrc[s * H + h]) + adn;
        e = (e > 0.f) ? e : 0.2f * e;
        float wv = expf(e - m) * invden;
        if (attn && lane == 0) attn[__ldg(&g_eid[j])] = wv;
        const float* hp = hfeat + (size_t)s * HC + h * CC;
        #pragma unroll
        for (int k = 0; k < 7; k++) {
            int c = lane + 32 * k;
            if (c < CC) acc[k] += wv * __ldg(hp + c);
        }
    }

    // epilogue: bias + GELU + outputs
    const float kc = 0.70710678118654752f;
    #pragma unroll
    for (int k = 0; k < 7; k++) {
        int c = lane + 32 * k;
        if (c < CC) {
            float v = acc[k] + __ldg(&bias[h * CC + c]);
            v = 0.5f * v * (1.f + erff(v * kc));
            if (out) out[(size_t)n * HC + h * CC + c] = v;
            if (ahi_o) {
                size_t base = (size_t)n * 800 + h * CC + c;
                __nv_bfloat16 hi, lo;
                bf16_split(v, hi, lo);
                ahi_o[base] = hi;
                alo_o[base] = lo;
            }
        }
    }
}

// ---------------- host launch ----------------
extern "C" void kernel_launch(void* const* d_in, const int* in_sizes, int n_in,
                              void* d_out, int out_size)
{
    const float* X  = (const float*)d_in[0];
    const int*   ei = (const int*)d_in[1];
    const float *W[5], *AS[5], *AD[5], *Bb[5];
    for (int i = 0; i < 5; i++) {
        W[i]  = (const float*)d_in[2 + 4 * i];
        AS[i] = (const float*)d_in[3 + 4 * i];
        AD[i] = (const float*)d_in[4 + 4 * i];
        Bb[i] = (const float*)d_in[5 + 4 * i];
    }
    float* out_x = (float*)d_out;
    float* out_a = out_x + (size_t)NN * 200;

    float *ph, *pas, *pad;
    __nv_bfloat16 *pahi, *palo, *pbhi, *pblo;
    cudaGetSymbolAddress((void**)&ph,  g_h);
    cudaGetSymbolAddress((void**)&pas, g_asrc);
    cudaGetSymbolAddress((void**)&pad, g_adst);
    cudaGetSymbolAddress((void**)&pahi, g_ahi);
    cudaGetSymbolAddress((void**)&palo, g_alo);
    cudaGetSymbolAddress((void**)&pbhi, g_bhi);
    cudaGetSymbolAddress((void**)&pblo, g_blo);

    cudaFuncSetAttribute(gemm_mma_kernel, cudaFuncAttributeMaxDynamicSharedMemorySize, GEMM_SMEM);

    // ---- CSR build ----
    zero_deg_kernel<<<div_up(NN, 256), 256>>>();
    hist_kernel<<<div_up(ET, 256), 256>>>(ei);
    scan_kernel<<<1, 1024>>>();
    cursor_kernel<<<div_up(NN, 256), 256>>>();
    scatter_kernel<<<div_up(ET, 256), 256>>>(ei);

    // pad rows for layers 1-4 A buffers
    zero_pad_kernel<<<div_up((NPAD - NN) * 800, 256), 256>>>();

    const int HEADS[5] = {4, 4, 4, 4, 1};
    const int FIN[5]   = {200, 800, 800, 800, 800};
    const int MT = NPAD / 128;   // 79 m-tiles

    for (int L = 0; L < 5; L++) {
        int H   = HEADS[L];
        int HC  = H * CC;
        int K   = FIN[L];
        int Kp  = (K + 31) & ~31;
        int NBT = div_up(HC, 80) * 80;   // 800 or 240

        if (L == 0)
            prep_a_kernel<<<div_up(NPAD * Kp, 256), 256>>>(X, K, Kp);
        prep_b_kernel<<<div_up(NBT * Kp, 256), 256>>>(W[L], K, Kp, HC, NBT);
        zero_alpha_kernel<<<div_up(NN * H, 256), 256>>>(NN * H);

        dim3 ggrid(MT, NBT / 80);
        gemm_mma_kernel<<<ggrid, 256, GEMM_SMEM>>>(
            pahi, palo, pbhi, pblo, ph, AS[L], AD[L], pas, pad, Kp, HC, H);

        float* outp  = (L == 4) ? out_x : nullptr;
        float* attnp = (L == 4) ? out_a : nullptr;
        __nv_bfloat16* hi_o = (L < 4) ? pahi : nullptr;
        __nv_bfloat16* lo_o = (L < 4) ? palo : nullptr;
        int nwarps = NN * H;
        agg_warp_kernel<<<div_up(nwarps * 32, 256), 256>>>(
            ph, Bb[L], outp, attnp, hi_o, lo_o, H, HC);
    }
    (void)in_sizes; (void)n_in; (void)out_size;
}

// round 14
// speedup vs baseline: 2.6199x; 1.0988x over previous
#include <cuda_runtime.h>
#include <cuda_bf16.h>
#include <math.h>
#include <stdint.h>

// Problem constants
#define NN 10000      // nodes
#define NPAD 10112    // padded rows (multiple of 128)
#define EE 100000     // raw edges
#define ET 110000     // edges + self loops
#define CC 200        // channels per head

// ---------------- device scratch ----------------
__device__ __align__(16) float g_h[NN * 800];
__device__ __align__(256) __nv_bfloat16 g_ahi[NPAD * 800];
__device__ __align__(256) __nv_bfloat16 g_alo[NPAD * 800];
__device__ __align__(256) __nv_bfloat16 g_bhi[800 * 800];
__device__ __align__(256) __nv_bfloat16 g_blo[800 * 800];
__device__ float g_asrc[NN * 4];
__device__ float g_adst[NN * 4];
__device__ int   g_deg[NN];
__device__ int   g_rowptr[NN + 1];
__device__ int   g_cursor[NN];
__device__ int   g_srcs[ET];
__device__ int   g_eid[ET];

static inline int div_up(int a, int b) { return (a + b - 1) / b; }

// ================= PTX helpers (base ISA only) =================
__device__ __forceinline__ uint32_t smem_u32(const void* p) {
    uint32_t a;
    asm("{ .reg .u64 t; cvta.to.shared.u64 t, %1; cvt.u32.u64 %0, t; }" : "=r"(a) : "l"(p));
    return a;
}
#define CP_ASYNC16(dst, src) \
    asm volatile("cp.async.cg.shared.global [%0], [%1], 16;" :: "r"(dst), "l"(src))
#define CP_COMMIT asm volatile("cp.async.commit_group;" ::: "memory")
#define CP_WAIT1  asm volatile("cp.async.wait_group 1;" ::: "memory")
#define CP_WAIT0  asm volatile("cp.async.wait_group 0;" ::: "memory")

__device__ __forceinline__ void ldsm_x4(uint32_t* r, uint32_t addr) {
    asm volatile("ldmatrix.sync.aligned.m8n8.x4.shared.b16 {%0,%1,%2,%3}, [%4];"
        : "=r"(r[0]), "=r"(r[1]), "=r"(r[2]), "=r"(r[3]) : "r"(addr));
}
__device__ __forceinline__ void ldsm_x2(uint32_t* r, uint32_t addr) {
    asm volatile("ldmatrix.sync.aligned.m8n8.x2.shared.b16 {%0,%1}, [%2];"
        : "=r"(r[0]), "=r"(r[1]) : "r"(addr));
}
__device__ __forceinline__ void mma_bf16(float* d, const uint32_t* a, const uint32_t* b) {
    asm volatile("mma.sync.aligned.m16n8k16.row.col.f32.bf16.bf16.f32 "
        "{%0,%1,%2,%3}, {%4,%5,%6,%7}, {%8,%9}, {%0,%1,%2,%3};"
        : "+f"(d[0]), "+f"(d[1]), "+f"(d[2]), "+f"(d[3])
        : "r"(a[0]), "r"(a[1]), "r"(a[2]), "r"(a[3]), "r"(b[0]), "r"(b[1]));
}

// ---------------- CSR build ----------------
__global__ void zero_deg_kernel() {
    int i = blockIdx.x * blockDim.x + threadIdx.x;
    if (i < NN) g_deg[i] = 0;
}
__global__ void hist_kernel(const int* __restrict__ ei) {
    int e = blockIdx.x * blockDim.x + threadIdx.x;
    if (e >= ET) return;
    int d = (e < EE) ? ei[EE + e] : (e - EE);
    atomicAdd(&g_deg[d], 1);
}
// scan also initializes g_cursor (fused cursor_kernel)
__global__ void scan_kernel() {
    __shared__ int sh[1024];
    __shared__ int carry;
    int tid = threadIdx.x;
    if (tid == 0) carry = 0;
    __syncthreads();
    for (int base = 0; base < NN; base += 1024) {
        int i = base + tid;
        int v = (i < NN) ? g_deg[i] : 0;
        int x = v;
        #pragma unroll
        for (int off = 1; off < 1024; off <<= 1) {
            sh[tid] = x;
            __syncthreads();
            if (tid >= off) x += sh[tid - off];
            __syncthreads();
        }
        if (i < NN) {
            int ex = carry + x - v;
            g_rowptr[i] = ex;
            g_cursor[i] = ex;
        }
        sh[tid] = x;
        __syncthreads();
        int total = sh[1023];
        __syncthreads();
        if (tid == 0) carry += total;
        __syncthreads();
    }
    if (threadIdx.x == 0) g_rowptr[NN] = carry;
}
__global__ void scatter_kernel(const int* __restrict__ ei) {
    int e = blockIdx.x * blockDim.x + threadIdx.x;
    if (e >= ET) return;
    int s, d;
    if (e < EE) { s = ei[e]; d = ei[EE + e]; }
    else        { s = e - EE; d = e - EE; }
    int pos = atomicAdd(&g_cursor[d], 1);
    g_srcs[pos] = s;
    g_eid[pos]  = e;
}

// ---------------- bf16 hi/lo prep ----------------
__device__ __forceinline__ void bf16_split(float v, __nv_bfloat16& h, __nv_bfloat16& l) {
    h = __float2bfloat16(v);
    l = __float2bfloat16(v - __bfloat162float(h));
}

// L0: X -> g_ahi/g_alo (Kp layout) AND zero pad rows for the Kp=800 layout (L1-4)
__global__ void prep_a_kernel(const float* __restrict__ A, int K, int Kp) {
    int idx = blockIdx.x * blockDim.x + threadIdx.x;
    int n0 = NPAD * Kp;
    int n1 = (NPAD - NN) * 800;
    if (idx < n0) {
        int row = idx / Kp;
        int k = idx - row * Kp;
        float v = (row < NN && k < K) ? A[(size_t)row * K + k] : 0.f;
        __nv_bfloat16 h, l;
        bf16_split(v, h, l);
        g_ahi[idx] = h;
        g_alo[idx] = l;
    }
    if (idx < n1) {
        int off = NN * 800 + idx;
        // L0 region is NPAD*Kp(=224) elems < NN*800, no overlap with pad region
        if (off >= n0) {
            g_ahi[off] = __float2bfloat16(0.f);
            g_alo[off] = __float2bfloat16(0.f);
        }
    }
}

// W [K, HC] -> transposed Bt [NBT][Kp]; rows >= HC zero. Also zeros alpha accums.
__global__ void prep_b_kernel(const float* __restrict__ W, int K, int Kp, int HC, int NBT, int NH) {
    int idx = blockIdx.x * blockDim.x + threadIdx.x;
    if (idx < NH) { g_asrc[idx] = 0.f; g_adst[idx] = 0.f; }
    int total = NBT * Kp;
    if (idx >= total) return;
    int n = idx / Kp;
    int k = idx - n * Kp;
    float v = (n < HC && k < K) ? W[(size_t)k * HC + n] : 0.f;
    __nv_bfloat16 hi, lo;
    bf16_split(v, hi, lo);
    g_bhi[idx] = hi;
    g_blo[idx] = lo;
}

// ================= mma.sync bf16-split GEMM =================
// Block tile 128(M) x 80(N), 8 warps = 4m x 2n, warp tile 32x40.
// 3-stage cp.async pipeline, one __syncthreads per K-iteration.
// Alpha dots via head-split buckets + atomicAdd.
#define SA_LO 8192u
#define SB_HI 16384u
#define SB_LO 21504u
#define STAGE 26624u
#define NSTAGE 3
#define CSTRIDE 88
#define GEMM_SMEM (NSTAGE * 26624)

__device__ __forceinline__ uint32_t swz(int r, int c) {
    return (uint32_t)(r * 64 + ((c ^ ((r >> 1) & 3)) << 4));
}

__device__ __forceinline__ void fill_stage(
    uint32_t su, int buf, int k0,
    const __nv_bfloat16* __restrict__ ahi, const __nv_bfloat16* __restrict__ alo,
    const __nv_bfloat16* __restrict__ bh, const __nv_bfloat16* __restrict__ bl,
    int Kp, int row0, int tid)
{
    uint32_t sb = su + (uint32_t)buf * STAGE;
    #pragma unroll
    for (int it = 0; it < 2; it++) {
        int j = tid + it * 256;
        int r = j >> 2, c = j & 3;
        uint32_t da = sb + swz(r, c);
        const char* sa = (const char*)(ahi + (size_t)(row0 + r) * Kp + k0) + c * 16;
        CP_ASYNC16(da, sa);
        const char* sl = (const char*)(alo + (size_t)(row0 + r) * Kp + k0) + c * 16;
        CP_ASYNC16(da + SA_LO, sl);
    }
    #pragma unroll
    for (int j0 = 0; j0 < 320; j0 += 256) {
        int j = j0 + tid;
        if (j < 320) {
            int r = j >> 2, c = j & 3;
            uint32_t db = sb + SB_HI + swz(r, c);
            const char* sh = (const char*)(bh + (size_t)r * Kp + k0) + c * 16;
            CP_ASYNC16(db, sh);
            const char* sl = (const char*)(bl + (size_t)r * Kp + k0) + c * 16;
            CP_ASYNC16(db + (SB_LO - SB_HI), sl);
        }
    }
}

__device__ __forceinline__ void load_b_frags(
    uint32_t bb[5][2], uint32_t sb, uint32_t plane_off, int kk, int nw, int lane)
{
    int g = lane >> 3;
    #pragma unroll
    for (int p = 0; p < 2; p++) {
        int nf = p * 2;
        int r = nw * 40 + (nf + (g >> 1)) * 8 + (lane & 7);
        int ch = 2 * kk + (g & 1);
        uint32_t addr = sb + SB_HI + plane_off + swz(r, ch);
        uint32_t t[4];
        ldsm_x4(t, addr);
        bb[nf][0] = t[0]; bb[nf][1] = t[1];
        bb[nf + 1][0] = t[2]; bb[nf + 1][1] = t[3];
    }
    int r = nw * 40 + 32 + (lane & 7);
    int ch = 2 * kk + ((lane >> 3) & 1);
    ldsm_x2(bb[4], sb + SB_HI + plane_off + swz(r, ch));
}

__global__ __launch_bounds__(256, 2) void gemm_mma_kernel(
    const __nv_bfloat16* __restrict__ Ahi, const __nv_bfloat16* __restrict__ Alo,
    const __nv_bfloat16* __restrict__ Bhi, const __nv_bfloat16* __restrict__ Blo,
    float* __restrict__ C,
    const float* __restrict__ asv_g, const float* __restrict__ adv_g,
    float* __restrict__ asrc_o, float* __restrict__ adst_o,
    int Kp, int HC, int H)
{
    extern __shared__ char smem[];
    uint32_t su = smem_u32(smem);
    int tid = threadIdx.x;
    int w = tid >> 5, lane = tid & 31;
    int mw = w >> 1, nw = w & 1;
    int bm = blockIdx.x, bn = blockIdx.y;
    int row0 = bm * 128;
    int col0 = bn * 80;

    const __nv_bfloat16* bhp = Bhi + (size_t)col0 * Kp;
    const __nv_bfloat16* blp = Blo + (size_t)col0 * Kp;

    float acc[2][5][4];
    #pragma unroll
    for (int mf = 0; mf < 2; mf++)
        #pragma unroll
        for (int nf = 0; nf < 5; nf++)
            #pragma unroll
            for (int q = 0; q < 4; q++) acc[mf][nf][q] = 0.f;

    int niter = Kp >> 5;
    fill_stage(su, 0, 0, Ahi, Alo, bhp, blp, Kp, row0, tid);
    CP_COMMIT;
    fill_stage(su, 1, 32, Ahi, Alo, bhp, blp, Kp, row0, tid);
    CP_COMMIT;

    for (int i = 0; i < niter; i++) {
        CP_WAIT1;
        __syncthreads();
        if (i + 2 < niter)
            fill_stage(su, (i + 2) % NSTAGE, (i + 2) * 32,
                       Ahi, Alo, bhp, blp, Kp, row0, tid);
        CP_COMMIT;

        uint32_t sb = su + (uint32_t)(i % NSTAGE) * STAGE;
        #pragma unroll
        for (int kk = 0; kk < 2; kk++) {
            uint32_t ah[2][4], al[2][4];
            #pragma unroll
            for (int mf = 0; mf < 2; mf++) {
                int r = mw * 32 + mf * 16 + (lane & 7) + ((lane >> 3) & 1) * 8;
                int ch = 2 * kk + (lane >> 4);
                uint32_t addr = sb + swz(r, ch);
                ldsm_x4(ah[mf], addr);
                ldsm_x4(al[mf], addr + SA_LO);
            }
            uint32_t bb[5][2];
            load_b_frags(bb, sb, 0u, kk, nw, lane);
            #pragma unroll
            for (int nf = 0; nf < 5; nf++)
                #pragma unroll
                for (int mf = 0; mf < 2; mf++)
                    mma_bf16(acc[mf][nf], ah[mf], bb[nf]);
            #pragma unroll
            for (int nf = 0; nf < 5; nf++)
                #pragma unroll
                for (int mf = 0; mf < 2; mf++)
                    mma_bf16(acc[mf][nf], al[mf], bb[nf]);
            load_b_frags(bb, sb, SB_LO - SB_HI, kk, nw, lane);
            #pragma unroll
            for (int nf = 0; nf < 5; nf++)
                #pragma unroll
                for (int mf = 0; mf < 2; mf++)
                    mma_bf16(acc[mf][nf], ah[mf], bb[nf]);
        }
    }
    CP_WAIT0;
    __syncthreads();

    // ---- epilogue: frags -> smem ----
    float* Cs = (float*)smem;
    #pragma unroll
    for (int mf = 0; mf < 2; mf++) {
        #pragma unroll
        for (int nf = 0; nf < 5; nf++) {
            int r0 = mw * 32 + mf * 16 + (lane >> 2);
            int cb = nw * 40 + nf * 8 + 2 * (lane & 3);
            *(float2*)&Cs[r0 * CSTRIDE + cb] = make_float2(acc[mf][nf][0], acc[mf][nf][1]);
            *(float2*)&Cs[(r0 + 8) * CSTRIDE + cb] = make_float2(acc[mf][nf][2], acc[mf][nf][3]);
        }
    }
    __syncthreads();

    // alpha dots with head-split buckets; warp w handles rows w*16..w*16+15
    int h0 = col0 / CC;
    int hb = (h0 + 1) * CC - col0;   // local cols >= hb belong to head h0+1
    #pragma unroll
    for (int i = 0; i < 16; i++) {
        int r = w * 16 + i;
        int gr = row0 + r;
        float sa0 = 0.f, sa1 = 0.f, sd0 = 0.f, sd1 = 0.f;
        #pragma unroll
        for (int cc = 0; cc < 3; cc++) {
            int c = lane + cc * 32;
            int gc = col0 + c;
            if (c < 80 && gc < HC) {
                float v = Cs[r * CSTRIDE + c];
                float pa = v * __ldg(asv_g + gc);
                float pd = v * __ldg(adv_g + gc);
                if (c < hb) { sa0 += pa; sd0 += pd; }
                else        { sa1 += pa; sd1 += pd; }
            }
        }
        #pragma unroll
        for (int o = 16; o; o >>= 1) {
            sa0 += __shfl_xor_sync(0xffffffffu, sa0, o);
            sa1 += __shfl_xor_sync(0xffffffffu, sa1, o);
            sd0 += __shfl_xor_sync(0xffffffffu, sd0, o);
            sd1 += __shfl_xor_sync(0xffffffffu, sd1, o);
        }
        if (lane == 0 && gr < NN) {
            atomicAdd(&asrc_o[gr * H + h0], sa0);
            atomicAdd(&adst_o[gr * H + h0], sd0);
            if (hb < 80 && h0 + 1 < H) {
                atomicAdd(&asrc_o[gr * H + h0 + 1], sa1);
                atomicAdd(&adst_o[gr * H + h0 + 1], sd1);
            }
        }
    }

    // coalesced store of real columns
    for (int idx = tid; idx < 128 * 80; idx += 256) {
        int r = idx / 80;
        int c = idx - r * 80;
        int gr = row0 + r;
        int gc = col0 + c;
        if (gr < NN && gc < HC)
            C[(size_t)gr * HC + gc] = Cs[r * CSTRIDE + c];
    }
}

// ---------------- segment softmax + aggregation: one warp per (node, head) ----------------
// Single-pass online softmax with accumulator rescaling; float4 feature gather.
// Lane owns float4 channel chunks c4 = lane and 32+lane (50 chunks total).
__global__ __launch_bounds__(256) void agg_warp_kernel(
    const float* __restrict__ hfeat, const float* __restrict__ bias,
    float* __restrict__ out, float* __restrict__ attn,
    __nv_bfloat16* __restrict__ ahi_o, __nv_bfloat16* __restrict__ alo_o,
    int H, int HC)
{
    int gw = (blockIdx.x * blockDim.x + threadIdx.x) >> 5;
    int lane = threadIdx.x & 31;
    if (gw >= NN * H) return;
    int n = gw / H;
    int h = gw - n * H;

    int start = g_rowptr[n];
    int end   = g_rowptr[n + 1];
    float adn = g_adst[n * H + h];

    int c40 = lane;           // always < 50
    int c41 = 32 + lane;
    bool act1 = (c41 < 50);

    float m = -1e30f, den = 0.f;
    float4 A0 = make_float4(0.f, 0.f, 0.f, 0.f);
    float4 A1 = A0;

    for (int j = start; j < end; j++) {
        int s = __ldg(&g_srcs[j]);
        float e = __ldg(&g_asrc[s * H + h]) + adn;
        e = (e > 0.f) ? e : 0.2f * e;
        float mn = fmaxf(m, e);
        float sc = expf(m - mn);     // first iter: expf(-inf)=0
        float p  = expf(e - mn);
        den = den * sc + p;
        const float* hp = hfeat + (size_t)s * HC + h * CC;
        float4 v0 = *(const float4*)(hp + 4 * c40);
        A0.x = A0.x * sc + p * v0.x;
        A0.y = A0.y * sc + p * v0.y;
        A0.z = A0.z * sc + p * v0.z;
        A0.w = A0.w * sc + p * v0.w;
        if (act1) {
            float4 v1 = *(const float4*)(hp + 4 * c41);
            A1.x = A1.x * sc + p * v1.x;
            A1.y = A1.y * sc + p * v1.y;
            A1.z = A1.z * sc + p * v1.z;
            A1.w = A1.w * sc + p * v1.w;
        }
        m = mn;
    }
    float invden = 1.f / den;

    // attn (last layer only): short second sweep with final (m, invden)
    if (attn && lane == 0) {
        for (int j = start; j < end; j++) {
            int s = __ldg(&g_srcs[j]);
            float e = __ldg(&g_asrc[s * H + h]) + adn;
            e = (e > 0.f) ? e : 0.2f * e;
            attn[__ldg(&g_eid[j])] = expf(e - m) * invden;
        }
    }

    // epilogue: normalize + bias + GELU + vectorized outputs
    const float kc = 0.70710678118654752f;
    #pragma unroll
    for (int k = 0; k < 2; k++) {
        int c4 = (k == 0) ? c40 : c41;
        if (k == 1 && !act1) break;
        float4 a = (k == 0) ? A0 : A1;
        float4 b4 = *(const float4*)&bias[h * CC + 4 * c4];
        float4 o4;
        o4.x = a.x * invden + b4.x;
        o4.y = a.y * invden + b4.y;
        o4.z = a.z * invden + b4.z;
        o4.w = a.w * invden + b4.w;
        o4.x = 0.5f * o4.x * (1.f + erff(o4.x * kc));
        o4.y = 0.5f * o4.y * (1.f + erff(o4.y * kc));
        o4.z = 0.5f * o4.z * (1.f + erff(o4.z * kc));
        o4.w = 0.5f * o4.w * (1.f + erff(o4.w * kc));
        if (out) *(float4*)&out[(size_t)n * HC + h * CC + 4 * c4] = o4;
        if (ahi_o) {
            size_t base = (size_t)n * 800 + h * CC + 4 * c4;
            __nv_bfloat16 hx, lx, hy, ly, hz, lz, hw, lw;
            bf16_split(o4.x, hx, lx); bf16_split(o4.y, hy, ly);
            bf16_split(o4.z, hz, lz); bf16_split(o4.w, hw, lw);
            *(__nv_bfloat162*)&ahi_o[base]     = __nv_bfloat162(hx, hy);
            *(__nv_bfloat162*)&ahi_o[base + 2] = __nv_bfloat162(hz, hw);
            *(__nv_bfloat162*)&alo_o[base]     = __nv_bfloat162(lx, ly);
            *(__nv_bfloat162*)&alo_o[base + 2] = __nv_bfloat162(lz, lw);
        }
    }
}

// ---------------- host launch ----------------
extern "C" void kernel_launch(void* const* d_in, const int* in_sizes, int n_in,
                              void* d_out, int out_size)
{
    const float* X  = (const float*)d_in[0];
    const int*   ei = (const int*)d_in[1];
    const float *W[5], *AS[5], *AD[5], *Bb[5];
    for (int i = 0; i < 5; i++) {
        W[i]  = (const float*)d_in[2 + 4 * i];
        AS[i] = (const float*)d_in[3 + 4 * i];
        AD[i] = (const float*)d_in[4 + 4 * i];
        Bb[i] = (const float*)d_in[5 + 4 * i];
    }
    float* out_x = (float*)d_out;
    float* out_a = out_x + (size_t)NN * 200;

    float *ph, *pas, *pad;
    __nv_bfloat16 *pahi, *palo, *pbhi, *pblo;
    cudaGetSymbolAddress((void**)&ph,  g_h);
    cudaGetSymbolAddress((void**)&pas, g_asrc);
    cudaGetSymbolAddress((void**)&pad, g_adst);
    cudaGetSymbolAddress((void**)&pahi, g_ahi);
    cudaGetSymbolAddress((void**)&palo, g_alo);
    cudaGetSymbolAddress((void**)&pbhi, g_bhi);
    cudaGetSymbolAddress((void**)&pblo, g_blo);

    cudaFuncSetAttribute(gemm_mma_kernel, cudaFuncAttributeMaxDynamicSharedMemorySize, GEMM_SMEM);

    // ---- CSR build ----
    zero_deg_kernel<<<div_up(NN, 256), 256>>>();
    hist_kernel<<<div_up(ET, 256), 256>>>(ei);
    scan_kernel<<<1, 1024>>>();          // also writes g_cursor
    scatter_kernel<<<div_up(ET, 256), 256>>>(ei);

    const int HEADS[5] = {4, 4, 4, 4, 1};
    const int FIN[5]   = {200, 800, 800, 800, 800};
    const int MT = NPAD / 128;   // 79 m-tiles

    for (int L = 0; L < 5; L++) {
        int H   = HEADS[L];
        int HC  = H * CC;
        int K   = FIN[L];
        int Kp  = (K + 31) & ~31;
        int NBT = div_up(HC, 80) * 80;   // 800 or 240

        if (L == 0) {
            int n0 = NPAD * Kp;                    // L0 split range
            int n1 = (NPAD - NN) * 800;            // pad-zero range
            int mx = (n0 > n1) ? n0 : n1;
            prep_a_kernel<<<div_up(mx, 256), 256>>>(X, K, Kp);
        }
        // prep_b also zeroes g_asrc/g_adst (NBT*Kp >= NN*H always)
        prep_b_kernel<<<div_up(NBT * Kp, 256), 256>>>(W[L], K, Kp, HC, NBT, NN * H);

        dim3 ggrid(MT, NBT / 80);
        gemm_mma_kernel<<<ggrid, 256, GEMM_SMEM>>>(
            pahi, palo, pbhi, pblo, ph, AS[L], AD[L], pas, pad, Kp, HC, H);

        float* outp  = (L == 4) ? out_x : nullptr;
        float* attnp = (L == 4) ? out_a : nullptr;
        __nv_bfloat16* hi_o = (L < 4) ? pahi : nullptr;
        __nv_bfloat16* lo_o = (L < 4) ? palo : nullptr;
        int nwarps = NN * H;
        agg_warp_kernel<<<div_up(nwarps * 32, 256), 256>>>(
            ph, Bb[L], outp, attnp, hi_o, lo_o, H, HC);
    }
    (void)in_sizes; (void)n_in; (void)out_size;
}